// round 12
// baseline (speedup 1.0000x reference)
#include <cuda_runtime.h>
#include <cstdint>
#include <cstddef>

// ---------------------------------------------------------------------------
// QAOA diff quantum simulator, N=18 qubits, B=8, 4 layers.
// R12: R11 structure (lane-major LDG/STG, ONE smem exchange + shuffle
//      butterflies, bit-sliced hp, PDL) at EPT=8 / 32KB smem / 4 CTAs/SM,
//      grid=512 (one full wave, 2x warps of R11).
//
// element = amp pair (amp bit0): float4 {re0,re1,im0,im1}; e-space 17 bits
//   = cb(6) + L(11) = tid(8) + r(3).
// Residencies:
//   X: L=(t&31) | r<<5 | (t>>5)<<8    regs=L5..7, lanes=L0..4, warp=L8..10
//   Y: L=t | r<<8                      regs=L8..10, lanes=L0..4, warp=L5..7
//   Z: L=r | (t&31)<<3 | (t>>5)<<8    regs=L0..2, 8 consec elements (P1)
// Layouts:
//   A: e = cb<<11 | L                      (leftover = cb = amp12..17)
//   B: L0,L1->e0,1; cb->e2..7; L8..10->e8..10; L2..7->e11..16
//                                          (leftover = cb = amp3..8)
//   => pre (prev leftover) == L2..7 in BOTH layouts
//      = X regs (L5..7, btf3) + shfl masks 4,8,16 (L2..4).
// Down pass: LDG(X,dense) -> pre{btf3 + shfl 4,8,16} -> phi ->
//   main{btf3 L5..7, shfl5 L0..4, amp0 swap} -> X->Y exchange (1 barrier)
//   -> btf3 L8..10 -> STG(Y,dense).
// ---------------------------------------------------------------------------

namespace {
constexpr int NQ   = 18;
constexpr int QDIM = 1 << NQ;             // 262144 amps
constexpr int EDIM = QDIM / 2;            // 131072 elements
constexpr int NB   = 8;
constexpr int NL   = 4;
constexpr int TPB  = 256;
constexpr int EPT  = 8;                   // elements per thread (r = 3 bits)
constexpr int CHUNKE = TPB * EPT;         // 2048 elements (11 bits)
constexpr int CPB  = EDIM / CHUNKE;       // 64
constexpr int BLOCKS = NB * CPB;          // 512 (one wave at 4 CTAs/SM)
constexpr size_t SMEM_BYTES = (size_t)CHUNKE * 16; // 32 KB
}

__device__ __align__(256) float4 g_state[(size_t)NB * EDIM]; // 16 MB
__device__ __align__(16) unsigned char g_hp[(size_t)NB * QDIM]; // 2 MB

// --------------------------- packed f32x2 helpers ---------------------------

using u64 = unsigned long long;

__device__ __forceinline__ u64 pk2(float lo, float hi) {
  u64 d; asm("mov.b64 %0, {%1, %2};" : "=l"(d) : "f"(lo), "f"(hi)); return d;
}
__device__ __forceinline__ void upk2(float& lo, float& hi, u64 v) {
  asm("mov.b64 {%0, %1}, %2;" : "=f"(lo), "=f"(hi) : "l"(v));
}
__device__ __forceinline__ u64 mul2(u64 a, u64 b) {
  u64 d; asm("mul.rn.f32x2 %0, %1, %2;" : "=l"(d) : "l"(a), "l"(b)); return d;
}
__device__ __forceinline__ u64 fma2(u64 a, u64 b, u64 c) {
  u64 d; asm("fma.rn.f32x2 %0, %1, %2, %3;" : "=l"(d) : "l"(a), "l"(b), "l"(c));
  return d;
}
__device__ __forceinline__ u64 swp2(u64 v) {
  float lo, hi; upk2(lo, hi, v); return pk2(hi, lo);
}

struct El { u64 re, im; };

__device__ __forceinline__ void rot2(El& x, El& y, u64 cc, u64 ss, u64 ns) {
  u64 t1 = mul2(ss, y.im);
  u64 t2 = mul2(ns, y.re);
  u64 t3 = mul2(ss, x.im);
  u64 t4 = mul2(ns, x.re);
  x.re = fma2(cc, x.re, t1);
  x.im = fma2(cc, x.im, t2);
  y.re = fma2(cc, y.re, t3);
  y.im = fma2(cc, y.im, t4);
}
__device__ __forceinline__ void rot2_lane(El& x, u64 cc, u64 ss, u64 ns) {
  u64 sre = swp2(x.re), sim = swp2(x.im);
  x.re = fma2(cc, x.re, mul2(ss, sim));
  x.im = fma2(cc, x.im, mul2(ns, sre));
}
__device__ __forceinline__ void rot2_shfl(El& x, int m, u64 cc, u64 ss, u64 ns) {
  u64 pre = __shfl_xor_sync(0xffffffffu, x.re, m);
  u64 pim = __shfl_xor_sync(0xffffffffu, x.im, m);
  x.re = fma2(cc, x.re, mul2(ss, pim));
  x.im = fma2(cc, x.im, mul2(ns, pre));
}

template<int P>
__device__ __forceinline__ void btfE(El* a, u64 cc, u64 ss, u64 ns) {
#pragma unroll
  for (int h = 0; h < EPT / 2; h++) {
    int i0 = ((h >> P) << (P + 1)) | (h & ((1 << P) - 1));
    rot2(a[i0], a[i0 | (1 << P)], cc, ss, ns);
  }
}
__device__ __forceinline__ void btf3(El* a, u64 cc, u64 ss, u64 ns) {
  btfE<0>(a, cc, ss, ns); btfE<1>(a, cc, ss, ns); btfE<2>(a, cc, ss, ns);
}
// lane bits via shuffle: masks 16..1 = L4..L0 (at X/Z lane==L0..4 or L3..7)
__device__ __forceinline__ void shfl5(El* a, u64 cc, u64 ss, u64 ns) {
#pragma unroll
  for (int m = 16; m >= 1; m >>= 1)
#pragma unroll
    for (int r = 0; r < EPT; r++) rot2_shfl(a[r], m, cc, ss, ns);
}
__device__ __forceinline__ void shfl3hi(El* a, u64 cc, u64 ss, u64 ns) {
#pragma unroll
  for (int m = 16; m >= 4; m >>= 1)
#pragma unroll
    for (int r = 0; r < EPT; r++) rot2_shfl(a[r], m, cc, ss, ns);
}

__device__ __forceinline__ void ph2(El& x, float2 p0, float2 p1) {
  u64 C  = pk2(p0.x, p1.x);
  u64 S  = pk2(p0.y, p1.y);
  u64 nS = pk2(-p0.y, -p1.y);
  u64 t = mul2(S, x.im);
  u64 u = mul2(nS, x.re);
  x.re = fma2(C, x.re, t);
  x.im = fma2(C, x.im, u);
}

// --------------------------- mappings ---------------------------------------

__device__ __forceinline__ int swz(int s) { return s ^ ((s >> 3) & 7); }

template<int LAY>
__device__ __forceinline__ int dmap(int cb, int L) {
  if (LAY == 0)   // A: cb = e11..16 (amp12..17)
    return (cb << 11) | L;
  else            // B: L0,1->e0,1; cb->e2..7; L8..10->e8..10; L2..7->e11..16
    return (L & 3) | (cb << 2) | (((L >> 8) & 7) << 8)
         | (((L >> 2) & 63) << 11);
}
__device__ __forceinline__ int locX(int t, int r) { return (t & 31) | (r << 5) | ((t >> 5) << 8); }
__device__ __forceinline__ int locY(int t, int r) { return t | (r << 8); }
__device__ __forceinline__ int locZ(int t, int r) { return r | ((t & 31) << 3) | ((t >> 5) << 8); }

// --------------------------- element I/O -------------------------------------

__device__ __forceinline__ El ld_el(const float4* p, int e) {
  float4 v = p[e];
  El x; x.re = pk2(v.x, v.y); x.im = pk2(v.z, v.w); return x;
}
__device__ __forceinline__ void st_el(float4* p, int e, El x) {
  float4 v; upk2(v.x, v.y, x.re); upk2(v.z, v.w, x.im);
  p[e] = v;
}

__device__ __forceinline__ void pdl_wait() {
  asm volatile("griddepcontrol.wait;" ::: "memory");
}

// exchange to Y, rotate L8..10, dense STG.
template<int LAY, int LOCSRC>
__device__ __forceinline__ void finish_Y(
    float4* sh, float4* st4, El* a, int cb, int tid,
    u64 ccm, u64 ssm, u64 nsm) {
#pragma unroll
  for (int r = 0; r < EPT; r++) {
    int s = (LOCSRC == 0) ? locX(tid, r) : locZ(tid, r);
    st_el(sh, swz(s), a[r]);
  }
  __syncthreads();
#pragma unroll
  for (int r = 0; r < EPT; r++) a[r] = ld_el(sh, swz(locY(tid, r)));
  btf3(a, ccm, ssm, nsm);   // L8..10
#pragma unroll
  for (int r = 0; r < EPT; r++)
    st_el(st4, dmap<LAY>(cb, locY(tid, r)), a[r]);
}

// --------------------------- P1: hp + init + phi1 + RX1 ----------------------

__global__ void __launch_bounds__(TPB, 4)
pass_init(const float* __restrict__ betas, const float* __restrict__ adj,
          float* __restrict__ out) {
  extern __shared__ float4 sh[];
  __shared__ float2 ph_tab[256];
  __shared__ int s_rm[NQ];
  __shared__ int s_sk[NQ];

  const int tid = threadIdx.x;
  const int b = blockIdx.x >> 6, cb = blockIdx.x & 63;

  { float sv, cv; sincosf((float)tid, &sv, &cv); ph_tab[tid] = make_float2(cv, sv); }
  if (tid < NQ) {
    int m = 0;
    const float* row = adj + (size_t)b * NQ * NQ + tid * NQ;
    for (int v = tid + 1; v < NQ; v++)
      if (row[v] > 0.5f) m |= 1 << (17 - v);
    s_rm[tid] = m;
    s_sk[tid] = __popc(m);
  }
  if (cb == 0 && tid == 0) out[b] = 0.f;
  float cm, sm; sincosf(betas[b * NL + 0], &sm, &cm);
  const u64 cc = pk2(cm, cm), ss = pk2(sm, sm), ns = pk2(-sm, -sm);
  __syncthreads();

  unsigned char* hpb = g_hp + (size_t)b * QDIM;
  float4* st4 = g_state + (size_t)b * EDIM;

  // ---- hp (bit-sliced) for this thread's 16 consecutive amps ----
  const int e0 = dmap<0>(cb, locZ(tid, 0));   // 8 consecutive elements
  const int dbase = e0 * 2;                   // 16 consecutive amps, 16B align
  unsigned int w[4];
  {
    int ne = 0;
#pragma unroll
    for (int u = 0; u < NQ; u++) ne += s_sk[u];

    // u < 14: sign fixed by dbase (j has only bits 0..3)
    int C0 = 0;
    int W2[4] = {0, 0, 0, 0};
#pragma unroll
    for (int u = 0; u < 14; u++) {
      const int m = s_rm[u];
      const int kk = s_sk[u] - 2 * __popc(dbase & m);
      const bool neg = (dbase >> (17 - u)) & 1;
      C0 += neg ? -kk : kk;
      const int d2 = neg ? -2 : 2;
#pragma unroll
      for (int bpos = 0; bpos < 4; bpos++)
        if ((m >> bpos) & 1) W2[bpos] += d2;
    }
    // u >= 14: sign bit lives in j (bit 17-u = 3..0)
    int kk4[4], ml4[4];
#pragma unroll
    for (int k = 0; k < 4; k++) {
      const int u = 14 + k;
      kk4[k] = s_sk[u] - 2 * __popc(dbase & s_rm[u]);
      ml4[k] = s_rm[u] & 15;
    }

    int cr[16];
#pragma unroll
    for (int j = 0; j < 16; j++) {
      int acc = C0;
#pragma unroll
      for (int bpos = 0; bpos < 4; bpos++)
        if (j & (1 << bpos)) acc -= W2[bpos];
#pragma unroll
      for (int k = 0; k < 4; k++) {
        int t2 = kk4[k] - 2 * __popc(j & ml4[k]);
        acc += ((j >> (3 - k)) & 1) ? -t2 : t2;
      }
      cr[j] = acc;
    }
#pragma unroll
    for (int q = 0; q < 4; q++) {
      unsigned int p = 0;
#pragma unroll
      for (int e = 0; e < 4; e++)
        p |= (unsigned int)((ne - cr[q * 4 + e]) >> 1) << (e * 8);
      w[q] = p;
    }
    *reinterpret_cast<uint4*>(hpb + dbase) = make_uint4(w[0], w[1], w[2], w[3]);
  }

  // ---- init + phi1 in Z (regs = L0..2, lanes = L3..7) ----
  El a[EPT];
  const float inv = 0.001953125f;  // 1/sqrt(2^18)
#pragma unroll
  for (int r = 0; r < EPT; r++) {
    int k0 = (w[r >> 1] >> ((r & 1) << 4)) & 0xFF;
    int k1 = (w[r >> 1] >> (((r & 1) << 4) + 8)) & 0xFF;
    float2 p0 = ph_tab[k0], p1 = ph_tab[k1];
    a[r].re = pk2(inv * p0.x, inv * p1.x);
    a[r].im = pk2(-inv * p0.y, -inv * p1.y);
  }
  btf3(a, cc, ss, ns);          // L0..2
  shfl5(a, cc, ss, ns);         // L3..7 (lane bits at Z)
#pragma unroll
  for (int r = 0; r < EPT; r++) rot2_lane(a[r], cc, ss, ns);  // amp0
  finish_Y<0, 1>(sh, st4, a, cb, tid, cc, ss, ns);            // L8..10 + STG
}

// --------------------------- down pass ---------------------------------------

template<int LAY>
__global__ void __launch_bounds__(TPB, 4)
pass_down(const float* __restrict__ betas, int pl) {
  extern __shared__ float4 sh[];
  __shared__ float2 ph_tab[256];

  const int tid = threadIdx.x;
  const int b = blockIdx.x >> 6, cb = blockIdx.x & 63;

  { float sv, cv; sincosf((float)tid, &sv, &cv); ph_tab[tid] = make_float2(cv, sv); }
  float cp, sp, cm, sm;
  sincosf(betas[b * NL + pl], &sp, &cp);
  sincosf(betas[b * NL + pl + 1], &sm, &cm);
  const u64 ccp = pk2(cp, cp), ssp = pk2(sp, sp), nsp = pk2(-sp, -sp);
  const u64 ccm = pk2(cm, cm), ssm = pk2(sm, sm), nsm = pk2(-sm, -sm);

  pdl_wait();

  const unsigned char* hpb = g_hp + (size_t)b * QDIM;
  float4* st4 = g_state + (size_t)b * EDIM;

  El a[EPT];
  unsigned short hw[EPT];
#pragma unroll
  for (int r = 0; r < EPT; r++) {
    int e = dmap<LAY>(cb, locX(tid, r));     // lanes dense on e0..4-ish
    a[r] = ld_el(st4, e);
    hw[r] = *reinterpret_cast<const unsigned short*>(hpb + 2 * (size_t)e);
  }
  __syncthreads();                           // ph_tab ready

  // pre = L2..7 (both layouts): regs L5..7 + shfl masks 16,8,4 (L4..L2)
  btf3(a, ccp, ssp, nsp);
  shfl3hi(a, ccp, ssp, nsp);
  // phi
#pragma unroll
  for (int r = 0; r < EPT; r++)
    ph2(a[r], ph_tab[hw[r] & 0xFF], ph_tab[hw[r] >> 8]);
  // main at X: regs L5..7, shfl L0..4, amp0
  btf3(a, ccm, ssm, nsm);
  shfl5(a, ccm, ssm, nsm);
#pragma unroll
  for (int r = 0; r < EPT; r++) rot2_lane(a[r], ccm, ssm, nsm);
  finish_Y<LAY, 0>(sh, st4, a, cb, tid, ccm, ssm, nsm);   // L8..10 + dense STG
}

// --------------------------- P5: pre RX4 + energy -----------------------------

__global__ void __launch_bounds__(TPB, 4)
pass_energy(const float* __restrict__ betas, float* __restrict__ out) {
  __shared__ float red[TPB / 32];

  const int tid = threadIdx.x;
  const int b = blockIdx.x >> 6, cb = blockIdx.x & 63;

  float cp, sp; sincosf(betas[b * NL + 3], &sp, &cp);
  const u64 ccp = pk2(cp, cp), ssp = pk2(sp, sp), nsp = pk2(-sp, -sp);

  pdl_wait();

  const unsigned char* hpb = g_hp + (size_t)b * QDIM;
  const float4* st4 = g_state + (size_t)b * EDIM;

  El a[EPT];
  unsigned short hw[EPT];
#pragma unroll
  for (int r = 0; r < EPT; r++) {
    int e = dmap<0>(cb, locX(tid, r));
    a[r] = ld_el(st4, e);
    hw[r] = *reinterpret_cast<const unsigned short*>(hpb + 2 * (size_t)e);
  }
  // pre RX4 = L2..7
  btf3(a, ccp, ssp, nsp);
  shfl3hi(a, ccp, ssp, nsp);

  float e = 0.f;
#pragma unroll
  for (int r = 0; r < EPT; r++) {
    u64 p2 = fma2(a[r].im, a[r].im, mul2(a[r].re, a[r].re));
    float p0, p1; upk2(p0, p1, p2);
    e = fmaf(p0, (float)(hw[r] & 0xFF), e);
    e = fmaf(p1, (float)(hw[r] >> 8), e);
  }
#pragma unroll
  for (int o = 16; o; o >>= 1) e += __shfl_down_sync(0xffffffffu, e, o);
  if ((tid & 31) == 0) red[tid >> 5] = e;
  __syncthreads();
  if (tid == 0) {
    float t = 0.f;
#pragma unroll
    for (int i = 0; i < TPB / 32; i++) t += red[i];
    atomicAdd(out + b, t);
  }
}

// --------------------------- launch ----------------------------------------

template<typename K, typename... Args>
static void launch_pdl(K kern, size_t smem, Args... args) {
  cudaLaunchConfig_t cfg = {};
  cfg.gridDim = dim3(BLOCKS, 1, 1);
  cfg.blockDim = dim3(TPB, 1, 1);
  cfg.dynamicSmemBytes = smem;
  cfg.stream = 0;
  cudaLaunchAttribute at[1];
  at[0].id = cudaLaunchAttributeProgrammaticStreamSerialization;
  at[0].val.programmaticStreamSerializationAllowed = 1;
  cfg.attrs = at;
  cfg.numAttrs = 1;
  cudaLaunchKernelEx(&cfg, kern, args...);
}

extern "C" void kernel_launch(void* const* d_in, const int* in_sizes, int n_in,
                              void* d_out, int out_size) {
  const float* betas = (const float*)d_in[0];
  const float* adj   = (const float*)d_in[1];
  if (n_in >= 2 && in_sizes[0] != NB * NL) {
    betas = (const float*)d_in[1];
    adj   = (const float*)d_in[0];
  }
  float* out = (float*)d_out;
  (void)out_size;

  cudaFuncSetAttribute(pass_init,    cudaFuncAttributeMaxDynamicSharedMemorySize, (int)SMEM_BYTES);
  cudaFuncSetAttribute(pass_down<0>, cudaFuncAttributeMaxDynamicSharedMemorySize, (int)SMEM_BYTES);
  cudaFuncSetAttribute(pass_down<1>, cudaFuncAttributeMaxDynamicSharedMemorySize, (int)SMEM_BYTES);

  pass_init<<<BLOCKS, TPB, SMEM_BYTES>>>(betas, adj, out);   // hp + phi1 + RX1
  launch_pdl(pass_down<1>, SMEM_BYTES, betas, 0);  // RX1 12..17, phi2, RX2
  launch_pdl(pass_down<0>, SMEM_BYTES, betas, 1);  // RX2 3..8,   phi3, RX3
  launch_pdl(pass_down<1>, SMEM_BYTES, betas, 2);  // RX3 12..17, phi4, RX4
  launch_pdl(pass_energy, 0, betas, out);          // RX4 3..8 + energy
}

// round 13
// speedup vs baseline: 1.0121x; 1.0121x over previous
#include <cuda_runtime.h>
#include <cstdint>
#include <cstddef>

// ---------------------------------------------------------------------------
// QAOA diff quantum simulator, N=18 qubits, B=8, 4 layers.
// R13: R11 (EPT=16, 2 CTAs/SM, lane-major dense LDG/STG, bit-sliced hp, PDL)
//      with the 5-stage lane-bit shuffle replaced by a second smem exchange:
//      X(regs L5..8) -> Z(regs L0..3) -> Y(regs L8..11); only ONE shuffle
//      stage remains (L4) + the intra-element amp0 swap.
//      Removes ~256 SHFL.32/thread (4 dependent ~30cyc stages) for
//      +32 LSU ops + 1 barrier.
//
// element = amp pair (amp bit0): float4 {re0,re1,im0,im1}; e-space 17 bits
//   = cb(5) + L(12) = tid(8) + r(4).
// Residencies:
//   X: L=(t&31) | r<<5 | (t>>5)<<9   regs=L5..8, lanes=L0..4, warp=L9..11
//   Z: L=r | (t&31)<<4 | (t>>5)<<9   regs=L0..3, lanes=L4..8, warp=L9..11
//   Y: L=t | r<<8                     regs=L8..11, lanes=L0..4, warp=L5..7
// Layouts:
//   A: e = cb<<12 | L                        (leftover cb = amp13..17)
//   B: L0..3->e0..3, cb->e4..8, L9..11->e9..11, L4->e12, L5..8->e13..16
//                                             (leftover cb = amp5..9)
//   => pre == L4..8 in both layouts = X regs (btf4) + shfl mask16 (L4).
// Down pass: LDG(X,dense) -> pre{btf4+shfl16} -> phi -> main btf4 (L5..8)
//   -> X->Z -> main{btf4 L0..3, shfl mask1 (L4), amp0 swap}
//   -> Z->Y -> btfE<1,2,3> (L9..11) -> STG(Y,dense).
// ---------------------------------------------------------------------------

namespace {
constexpr int NQ   = 18;
constexpr int QDIM = 1 << NQ;             // 262144 amps
constexpr int EDIM = QDIM / 2;            // 131072 elements
constexpr int NB   = 8;
constexpr int NL   = 4;
constexpr int TPB  = 256;
constexpr int EPT  = 16;                  // elements per thread
constexpr int CHUNKE = TPB * EPT;         // 4096 elements (12 bits)
constexpr int CPB  = EDIM / CHUNKE;       // 32
constexpr int BLOCKS = NB * CPB;          // 256
constexpr size_t SMEM_BYTES = (size_t)CHUNKE * 16; // 64 KB
}

__device__ __align__(256) float4 g_state[(size_t)NB * EDIM]; // 16 MB
__device__ __align__(16) unsigned char g_hp[(size_t)NB * QDIM]; // 2 MB

// --------------------------- packed f32x2 helpers ---------------------------

using u64 = unsigned long long;

__device__ __forceinline__ u64 pk2(float lo, float hi) {
  u64 d; asm("mov.b64 %0, {%1, %2};" : "=l"(d) : "f"(lo), "f"(hi)); return d;
}
__device__ __forceinline__ void upk2(float& lo, float& hi, u64 v) {
  asm("mov.b64 {%0, %1}, %2;" : "=f"(lo), "=f"(hi) : "l"(v));
}
__device__ __forceinline__ u64 mul2(u64 a, u64 b) {
  u64 d; asm("mul.rn.f32x2 %0, %1, %2;" : "=l"(d) : "l"(a), "l"(b)); return d;
}
__device__ __forceinline__ u64 fma2(u64 a, u64 b, u64 c) {
  u64 d; asm("fma.rn.f32x2 %0, %1, %2, %3;" : "=l"(d) : "l"(a), "l"(b), "l"(c));
  return d;
}
__device__ __forceinline__ u64 swp2(u64 v) {
  float lo, hi; upk2(lo, hi, v); return pk2(hi, lo);
}

struct El { u64 re, im; };

__device__ __forceinline__ void rot2(El& x, El& y, u64 cc, u64 ss, u64 ns) {
  u64 t1 = mul2(ss, y.im);
  u64 t2 = mul2(ns, y.re);
  u64 t3 = mul2(ss, x.im);
  u64 t4 = mul2(ns, x.re);
  x.re = fma2(cc, x.re, t1);
  x.im = fma2(cc, x.im, t2);
  y.re = fma2(cc, y.re, t3);
  y.im = fma2(cc, y.im, t4);
}
__device__ __forceinline__ void rot2_lane(El& x, u64 cc, u64 ss, u64 ns) {
  u64 sre = swp2(x.re), sim = swp2(x.im);
  x.re = fma2(cc, x.re, mul2(ss, sim));
  x.im = fma2(cc, x.im, mul2(ns, sre));
}
__device__ __forceinline__ void rot2_shfl(El& x, int m, u64 cc, u64 ss, u64 ns) {
  u64 pre = __shfl_xor_sync(0xffffffffu, x.re, m);
  u64 pim = __shfl_xor_sync(0xffffffffu, x.im, m);
  x.re = fma2(cc, x.re, mul2(ss, pim));
  x.im = fma2(cc, x.im, mul2(ns, pre));
}

template<int P>
__device__ __forceinline__ void btfE(El* a, u64 cc, u64 ss, u64 ns) {
#pragma unroll
  for (int h = 0; h < EPT / 2; h++) {
    int i0 = ((h >> P) << (P + 1)) | (h & ((1 << P) - 1));
    rot2(a[i0], a[i0 | (1 << P)], cc, ss, ns);
  }
}
__device__ __forceinline__ void btf4(El* a, u64 cc, u64 ss, u64 ns) {
  btfE<0>(a, cc, ss, ns); btfE<1>(a, cc, ss, ns);
  btfE<2>(a, cc, ss, ns); btfE<3>(a, cc, ss, ns);
}
// one shuffle stage over all 16 resident elements
__device__ __forceinline__ void shfl1(El* a, int m, u64 cc, u64 ss, u64 ns) {
#pragma unroll
  for (int r = 0; r < EPT; r++) rot2_shfl(a[r], m, cc, ss, ns);
}

__device__ __forceinline__ void ph2(El& x, float2 p0, float2 p1) {
  u64 C  = pk2(p0.x, p1.x);
  u64 S  = pk2(p0.y, p1.y);
  u64 nS = pk2(-p0.y, -p1.y);
  u64 t = mul2(S, x.im);
  u64 u = mul2(nS, x.re);
  x.re = fma2(C, x.re, t);
  x.im = fma2(C, x.im, u);
}

// --------------------------- mappings ---------------------------------------

__device__ __forceinline__ int swz(int s) { return s ^ ((s >> 4) & 15); }

template<int LAY>
__device__ __forceinline__ int dmap(int cb, int L) {
  if (LAY == 0)   // A: cb = e12..16 (amp13..17)
    return (cb << 12) | L;
  else            // B: L0..3->e0..3, cb->e4..8, L9..11->e9..11,
                  //    L4->e12, L5..8->e13..16
    return (L & 15) | (cb << 4) | (((L >> 9) & 7) << 9)
         | (((L >> 4) & 1) << 12) | (((L >> 5) & 15) << 13);
}
__device__ __forceinline__ int locX(int t, int r) { return (t & 31) | (r << 5) | ((t >> 5) << 9); }
__device__ __forceinline__ int locY(int t, int r) { return t | (r << 8); }
__device__ __forceinline__ int locZ(int t, int r) { return r | ((t & 31) << 4) | ((t >> 5) << 9); }

// --------------------------- element I/O -------------------------------------

__device__ __forceinline__ El ld_el(const float4* p, int e) {
  float4 v = p[e];
  El x; x.re = pk2(v.x, v.y); x.im = pk2(v.z, v.w); return x;
}
__device__ __forceinline__ void st_el(float4* p, int e, El x) {
  float4 v; upk2(v.x, v.y, x.re); upk2(v.z, v.w, x.im);
  p[e] = v;
}

__device__ __forceinline__ void pdl_wait() {
  asm volatile("griddepcontrol.wait;" ::: "memory");
}

// exchange helper: store in SRC pattern, barrier, reload in DST pattern.
// SRC/DST: 0 = X, 1 = Z, 2 = Y
template<int SRC, int DST>
__device__ __forceinline__ void exch(float4* sh, El* a, int tid) {
#pragma unroll
  for (int r = 0; r < EPT; r++) {
    int s = (SRC == 0) ? locX(tid, r) : (SRC == 1) ? locZ(tid, r) : locY(tid, r);
    st_el(sh, swz(s), a[r]);
  }
  __syncthreads();
#pragma unroll
  for (int r = 0; r < EPT; r++) {
    int s = (DST == 0) ? locX(tid, r) : (DST == 1) ? locZ(tid, r) : locY(tid, r);
    a[r] = ld_el(sh, swz(s));
  }
}

// --------------------------- P1: hp + init + phi1 + RX1 ----------------------

__global__ void __launch_bounds__(TPB, 2)
pass_init(const float* __restrict__ betas, const float* __restrict__ adj,
          float* __restrict__ out) {
  extern __shared__ float4 sh[];
  __shared__ float2 ph_tab[256];
  __shared__ int s_rm[NQ];
  __shared__ int s_sk[NQ];

  const int tid = threadIdx.x;
  const int b = blockIdx.x >> 5, cb = blockIdx.x & 31;

  { float sv, cv; sincosf((float)tid, &sv, &cv); ph_tab[tid] = make_float2(cv, sv); }
  if (tid < NQ) {
    int m = 0;
    const float* row = adj + (size_t)b * NQ * NQ + tid * NQ;
    for (int v = tid + 1; v < NQ; v++)
      if (row[v] > 0.5f) m |= 1 << (17 - v);
    s_rm[tid] = m;
    s_sk[tid] = __popc(m);
  }
  if (cb == 0 && tid == 0) out[b] = 0.f;
  float cm, sm; sincosf(betas[b * NL + 0], &sm, &cm);
  const u64 cc = pk2(cm, cm), ss = pk2(sm, sm), ns = pk2(-sm, -sm);
  __syncthreads();

  unsigned char* hpb = g_hp + (size_t)b * QDIM;
  float4* st4 = g_state + (size_t)b * EDIM;

  // ---- hp via bit-slicing (thread covers amps dbase..dbase+31) ----
  const int e0 = dmap<0>(cb, locZ(tid, 0));   // 16 consecutive elements
  const int dbase = e0 * 2;
  unsigned int w[8];
  {
    int ne = 0;
#pragma unroll
    for (int u = 0; u < NQ; u++) ne += s_sk[u];

    int C0 = 0;
    int W2[5] = {0, 0, 0, 0, 0};
#pragma unroll
    for (int u = 0; u < 13; u++) {
      const int m = s_rm[u];
      const int kk = s_sk[u] - 2 * __popc(dbase & m);
      const bool neg = (dbase >> (17 - u)) & 1;
      C0 += neg ? -kk : kk;
      const int d2 = neg ? -2 : 2;
#pragma unroll
      for (int bpos = 0; bpos < 5; bpos++)
        if ((m >> bpos) & 1) W2[bpos] += d2;
    }
    int kk5[5], ml5[5];
#pragma unroll
    for (int k = 0; k < 5; k++) {
      const int u = 13 + k;
      kk5[k] = s_sk[u] - 2 * __popc(dbase & s_rm[u]);
      ml5[k] = s_rm[u] & 31;
    }

    int cr[32];
#pragma unroll
    for (int j = 0; j < 32; j++) {
      int acc = C0;
#pragma unroll
      for (int bpos = 0; bpos < 5; bpos++)
        if (j & (1 << bpos)) acc -= W2[bpos];
#pragma unroll
      for (int k = 0; k < 5; k++) {
        int t2 = kk5[k] - 2 * __popc(j & ml5[k]);
        acc += ((j >> (4 - k)) & 1) ? -t2 : t2;
      }
      cr[j] = acc;
    }
#pragma unroll
    for (int q = 0; q < 8; q++) {
      unsigned int p = 0;
#pragma unroll
      for (int e = 0; e < 4; e++)
        p |= (unsigned int)((ne - cr[q * 4 + e]) >> 1) << (e * 8);
      w[q] = p;
    }
    uint4* hdst = reinterpret_cast<uint4*>(hpb + dbase);
    hdst[0] = make_uint4(w[0], w[1], w[2], w[3]);
    hdst[1] = make_uint4(w[4], w[5], w[6], w[7]);
  }

  // ---- init + phi1 at Z (regs = L0..3, lanes = L4..8) ----
  El a[EPT];
  const float inv = 0.001953125f;  // 1/sqrt(2^18)
#pragma unroll
  for (int r = 0; r < EPT; r++) {
    int k0 = (w[r >> 1] >> ((r & 1) << 4)) & 0xFF;
    int k1 = (w[r >> 1] >> (((r & 1) << 4) + 8)) & 0xFF;
    float2 p0 = ph_tab[k0], p1 = ph_tab[k1];
    a[r].re = pk2(inv * p0.x, inv * p1.x);
    a[r].im = pk2(-inv * p0.y, -inv * p1.y);
  }
  btf4(a, cc, ss, ns);                    // L0..3
  shfl1(a, 1, cc, ss, ns);                // L4 (lane bit 0 at Z)
#pragma unroll
  for (int r = 0; r < EPT; r++) rot2_lane(a[r], cc, ss, ns);  // amp0
  exch<1, 0>(sh, a, tid);                 // Z -> X
  btf4(a, cc, ss, ns);                    // L5..8
  exch<0, 2>(sh, a, tid);                 // X -> Y
  btfE<1>(a, cc, ss, ns);                 // L9
  btfE<2>(a, cc, ss, ns);                 // L10
  btfE<3>(a, cc, ss, ns);                 // L11
#pragma unroll
  for (int r = 0; r < EPT; r++)
    st_el(st4, dmap<0>(cb, locY(tid, r)), a[r]);   // dense
}

// --------------------------- down pass ---------------------------------------

template<int LAY>
__global__ void __launch_bounds__(TPB, 2)
pass_down(const float* __restrict__ betas, int pl) {
  extern __shared__ float4 sh[];
  __shared__ float2 ph_tab[256];

  const int tid = threadIdx.x;
  const int b = blockIdx.x >> 5, cb = blockIdx.x & 31;

  { float sv, cv; sincosf((float)tid, &sv, &cv); ph_tab[tid] = make_float2(cv, sv); }
  float cp, sp, cm, sm;
  sincosf(betas[b * NL + pl], &sp, &cp);
  sincosf(betas[b * NL + pl + 1], &sm, &cm);
  const u64 ccp = pk2(cp, cp), ssp = pk2(sp, sp), nsp = pk2(-sp, -sp);
  const u64 ccm = pk2(cm, cm), ssm = pk2(sm, sm), nsm = pk2(-sm, -sm);

  pdl_wait();

  const unsigned char* hpb = g_hp + (size_t)b * QDIM;
  float4* st4 = g_state + (size_t)b * EDIM;

  El a[EPT];
  unsigned short hw[EPT];
#pragma unroll
  for (int r = 0; r < EPT; r++) {
    int e = dmap<LAY>(cb, locX(tid, r));   // dense LDG
    a[r] = ld_el(st4, e);
    hw[r] = *reinterpret_cast<const unsigned short*>(hpb + 2 * (size_t)e);
  }
  __syncthreads();                         // ph_tab ready (overlaps loads)

  // pre = L4..8 (amp13..17 @B, amp5..9 @A): regs L5..8 + shfl mask16 (L4)
  btf4(a, ccp, ssp, nsp);
  shfl1(a, 16, ccp, ssp, nsp);
  // phi
#pragma unroll
  for (int r = 0; r < EPT; r++)
    ph2(a[r], ph_tab[hw[r] & 0xFF], ph_tab[hw[r] >> 8]);
  // main: L5..8 at X
  btf4(a, ccm, ssm, nsm);
  // X -> Z
  exch<0, 1>(sh, a, tid);
  // main: L0..3 (Z regs), L4 (lane bit 0 at Z), amp0
  btf4(a, ccm, ssm, nsm);
  shfl1(a, 1, ccm, ssm, nsm);
#pragma unroll
  for (int r = 0; r < EPT; r++) rot2_lane(a[r], ccm, ssm, nsm);
  // Z -> Y
  exch<1, 2>(sh, a, tid);
  // main: L9..11 (Y regs, L8 done at X)
  btfE<1>(a, ccm, ssm, nsm);
  btfE<2>(a, ccm, ssm, nsm);
  btfE<3>(a, ccm, ssm, nsm);
#pragma unroll
  for (int r = 0; r < EPT; r++)
    st_el(st4, dmap<LAY>(cb, locY(tid, r)), a[r]);   // dense STG
}

// --------------------------- P5: pre RX4 + energy -----------------------------

__global__ void __launch_bounds__(TPB, 2)
pass_energy(const float* __restrict__ betas, float* __restrict__ out) {
  __shared__ float red[TPB / 32];

  const int tid = threadIdx.x;
  const int b = blockIdx.x >> 5, cb = blockIdx.x & 31;

  float cp, sp; sincosf(betas[b * NL + 3], &sp, &cp);
  const u64 ccp = pk2(cp, cp), ssp = pk2(sp, sp), nsp = pk2(-sp, -sp);

  pdl_wait();

  const unsigned char* hpb = g_hp + (size_t)b * QDIM;
  const float4* st4 = g_state + (size_t)b * EDIM;

  El a[EPT];
  unsigned short hw[EPT];
#pragma unroll
  for (int r = 0; r < EPT; r++) {
    int e = dmap<0>(cb, locX(tid, r));
    a[r] = ld_el(st4, e);
    hw[r] = *reinterpret_cast<const unsigned short*>(hpb + 2 * (size_t)e);
  }
  // pre RX4 = L4..8
  btf4(a, ccp, ssp, nsp);
  shfl1(a, 16, ccp, ssp, nsp);

  float e = 0.f;
#pragma unroll
  for (int r = 0; r < EPT; r++) {
    u64 p2 = fma2(a[r].im, a[r].im, mul2(a[r].re, a[r].re));
    float p0, p1; upk2(p0, p1, p2);
    e = fmaf(p0, (float)(hw[r] & 0xFF), e);
    e = fmaf(p1, (float)(hw[r] >> 8), e);
  }
#pragma unroll
  for (int o = 16; o; o >>= 1) e += __shfl_down_sync(0xffffffffu, e, o);
  if ((tid & 31) == 0) red[tid >> 5] = e;
  __syncthreads();
  if (tid == 0) {
    float t = 0.f;
#pragma unroll
    for (int i = 0; i < TPB / 32; i++) t += red[i];
    atomicAdd(out + b, t);
  }
}

// --------------------------- launch ----------------------------------------

template<typename K, typename... Args>
static void launch_pdl(K kern, size_t smem, Args... args) {
  cudaLaunchConfig_t cfg = {};
  cfg.gridDim = dim3(BLOCKS, 1, 1);
  cfg.blockDim = dim3(TPB, 1, 1);
  cfg.dynamicSmemBytes = smem;
  cfg.stream = 0;
  cudaLaunchAttribute at[1];
  at[0].id = cudaLaunchAttributeProgrammaticStreamSerialization;
  at[0].val.programmaticStreamSerializationAllowed = 1;
  cfg.attrs = at;
  cfg.numAttrs = 1;
  cudaLaunchKernelEx(&cfg, kern, args...);
}

extern "C" void kernel_launch(void* const* d_in, const int* in_sizes, int n_in,
                              void* d_out, int out_size) {
  const float* betas = (const float*)d_in[0];
  const float* adj   = (const float*)d_in[1];
  if (n_in >= 2 && in_sizes[0] != NB * NL) {
    betas = (const float*)d_in[1];
    adj   = (const float*)d_in[0];
  }
  float* out = (float*)d_out;
  (void)out_size;

  cudaFuncSetAttribute(pass_init,    cudaFuncAttributeMaxDynamicSharedMemorySize, (int)SMEM_BYTES);
  cudaFuncSetAttribute(pass_down<0>, cudaFuncAttributeMaxDynamicSharedMemorySize, (int)SMEM_BYTES);
  cudaFuncSetAttribute(pass_down<1>, cudaFuncAttributeMaxDynamicSharedMemorySize, (int)SMEM_BYTES);

  pass_init<<<BLOCKS, TPB, SMEM_BYTES>>>(betas, adj, out);   // hp + phi1 + RX1
  launch_pdl(pass_down<1>, SMEM_BYTES, betas, 0);  // RX1 13..17, phi2, RX2
  launch_pdl(pass_down<0>, SMEM_BYTES, betas, 1);  // RX2 5..9,   phi3, RX3
  launch_pdl(pass_down<1>, SMEM_BYTES, betas, 2);  // RX3 13..17, phi4, RX4
  launch_pdl(pass_energy, 0, betas, out);          // RX4 5..9 + energy
}

// round 14
// speedup vs baseline: 1.0938x; 1.0806x over previous
#include <cuda_runtime.h>
#include <cuda_fp16.h>
#include <cstdint>
#include <cstddef>

// ---------------------------------------------------------------------------
// QAOA diff quantum simulator, N=18 qubits, B=8, 4 layers.
// R14: R13 (EPT=16, lane-major dense global access, X->Z->Y exchanges with
//      one shuffle stage, bit-sliced hp, PDL) + FP16 GLOBAL STATE:
//      global state stored as 4xfp16 per element (8B); all arithmetic and
//      smem exchanges remain fp32. Halves DRAM traffic (34->18 MB/pass),
//      LDG/STG event count, and L2 footprint (better inter-pass residency).
//      Precision: 4 rounding events/amp, norm-preserved, averaged over 2^18
//      terms in the energy sum -> ~1e-4 rel worst case (threshold 1e-3).
//
// Layouts / residencies identical to R13 (see comments there).
// ---------------------------------------------------------------------------

namespace {
constexpr int NQ   = 18;
constexpr int QDIM = 1 << NQ;             // 262144 amps
constexpr int EDIM = QDIM / 2;            // 131072 elements
constexpr int NB   = 8;
constexpr int NL   = 4;
constexpr int TPB  = 256;
constexpr int EPT  = 16;                  // elements per thread
constexpr int CHUNKE = TPB * EPT;         // 4096 elements (12 bits)
constexpr int CPB  = EDIM / CHUNKE;       // 32
constexpr int BLOCKS = NB * CPB;          // 256
constexpr size_t SMEM_BYTES = (size_t)CHUNKE * 16; // 64 KB (fp32 exchange)
}

__device__ __align__(256) uint2 g_state[(size_t)NB * EDIM];      // 8 MB fp16x4
__device__ __align__(16) unsigned char g_hp[(size_t)NB * QDIM];  // 2 MB

// --------------------------- packed f32x2 helpers ---------------------------

using u64 = unsigned long long;

__device__ __forceinline__ u64 pk2(float lo, float hi) {
  u64 d; asm("mov.b64 %0, {%1, %2};" : "=l"(d) : "f"(lo), "f"(hi)); return d;
}
__device__ __forceinline__ void upk2(float& lo, float& hi, u64 v) {
  asm("mov.b64 {%0, %1}, %2;" : "=f"(lo), "=f"(hi) : "l"(v));
}
__device__ __forceinline__ u64 mul2(u64 a, u64 b) {
  u64 d; asm("mul.rn.f32x2 %0, %1, %2;" : "=l"(d) : "l"(a), "l"(b)); return d;
}
__device__ __forceinline__ u64 fma2(u64 a, u64 b, u64 c) {
  u64 d; asm("fma.rn.f32x2 %0, %1, %2, %3;" : "=l"(d) : "l"(a), "l"(b), "l"(c));
  return d;
}
__device__ __forceinline__ u64 swp2(u64 v) {
  float lo, hi; upk2(lo, hi, v); return pk2(hi, lo);
}

struct El { u64 re, im; };

__device__ __forceinline__ void rot2(El& x, El& y, u64 cc, u64 ss, u64 ns) {
  u64 t1 = mul2(ss, y.im);
  u64 t2 = mul2(ns, y.re);
  u64 t3 = mul2(ss, x.im);
  u64 t4 = mul2(ns, x.re);
  x.re = fma2(cc, x.re, t1);
  x.im = fma2(cc, x.im, t2);
  y.re = fma2(cc, y.re, t3);
  y.im = fma2(cc, y.im, t4);
}
__device__ __forceinline__ void rot2_lane(El& x, u64 cc, u64 ss, u64 ns) {
  u64 sre = swp2(x.re), sim = swp2(x.im);
  x.re = fma2(cc, x.re, mul2(ss, sim));
  x.im = fma2(cc, x.im, mul2(ns, sre));
}
__device__ __forceinline__ void rot2_shfl(El& x, int m, u64 cc, u64 ss, u64 ns) {
  u64 pre = __shfl_xor_sync(0xffffffffu, x.re, m);
  u64 pim = __shfl_xor_sync(0xffffffffu, x.im, m);
  x.re = fma2(cc, x.re, mul2(ss, pim));
  x.im = fma2(cc, x.im, mul2(ns, pre));
}

template<int P>
__device__ __forceinline__ void btfE(El* a, u64 cc, u64 ss, u64 ns) {
#pragma unroll
  for (int h = 0; h < EPT / 2; h++) {
    int i0 = ((h >> P) << (P + 1)) | (h & ((1 << P) - 1));
    rot2(a[i0], a[i0 | (1 << P)], cc, ss, ns);
  }
}
__device__ __forceinline__ void btf4(El* a, u64 cc, u64 ss, u64 ns) {
  btfE<0>(a, cc, ss, ns); btfE<1>(a, cc, ss, ns);
  btfE<2>(a, cc, ss, ns); btfE<3>(a, cc, ss, ns);
}
__device__ __forceinline__ void shfl1(El* a, int m, u64 cc, u64 ss, u64 ns) {
#pragma unroll
  for (int r = 0; r < EPT; r++) rot2_shfl(a[r], m, cc, ss, ns);
}

__device__ __forceinline__ void ph2(El& x, float2 p0, float2 p1) {
  u64 C  = pk2(p0.x, p1.x);
  u64 S  = pk2(p0.y, p1.y);
  u64 nS = pk2(-p0.y, -p1.y);
  u64 t = mul2(S, x.im);
  u64 u = mul2(nS, x.re);
  x.re = fma2(C, x.re, t);
  x.im = fma2(C, x.im, u);
}

// --------------------------- mappings ---------------------------------------

__device__ __forceinline__ int swz(int s) { return s ^ ((s >> 4) & 15); }

template<int LAY>
__device__ __forceinline__ int dmap(int cb, int L) {
  if (LAY == 0)   // A: cb = e12..16 (amp13..17)
    return (cb << 12) | L;
  else            // B: L0..3->e0..3, cb->e4..8, L9..11->e9..11,
                  //    L4->e12, L5..8->e13..16
    return (L & 15) | (cb << 4) | (((L >> 9) & 7) << 9)
         | (((L >> 4) & 1) << 12) | (((L >> 5) & 15) << 13);
}
__device__ __forceinline__ int locX(int t, int r) { return (t & 31) | (r << 5) | ((t >> 5) << 9); }
__device__ __forceinline__ int locY(int t, int r) { return t | (r << 8); }
__device__ __forceinline__ int locZ(int t, int r) { return r | ((t & 31) << 4) | ((t >> 5) << 9); }

// --------------------------- element I/O -------------------------------------

// global (fp16x4)
__device__ __forceinline__ El ldg_el(const uint2* p, int e) {
  uint2 v = p[e];
  __half2 hre = *reinterpret_cast<__half2*>(&v.x);
  __half2 him = *reinterpret_cast<__half2*>(&v.y);
  float2 fre = __half22float2(hre);
  float2 fim = __half22float2(him);
  El x; x.re = pk2(fre.x, fre.y); x.im = pk2(fim.x, fim.y); return x;
}
__device__ __forceinline__ void stg_el(uint2* p, int e, El x) {
  float r0, r1, i0, i1;
  upk2(r0, r1, x.re);
  upk2(i0, i1, x.im);
  __half2 hre = __floats2half2_rn(r0, r1);
  __half2 him = __floats2half2_rn(i0, i1);
  uint2 v;
  v.x = *reinterpret_cast<unsigned int*>(&hre);
  v.y = *reinterpret_cast<unsigned int*>(&him);
  p[e] = v;
}
// shared (fp32)
__device__ __forceinline__ El lds_el(const float4* p, int s) {
  float4 v = p[s];
  El x; x.re = pk2(v.x, v.y); x.im = pk2(v.z, v.w); return x;
}
__device__ __forceinline__ void sts_el(float4* p, int s, El x) {
  float4 v; upk2(v.x, v.y, x.re); upk2(v.z, v.w, x.im);
  p[s] = v;
}

__device__ __forceinline__ void pdl_wait() {
  asm volatile("griddepcontrol.wait;" ::: "memory");
}

// exchange helper: SRC/DST: 0 = X, 1 = Z, 2 = Y
template<int SRC, int DST>
__device__ __forceinline__ void exch(float4* sh, El* a, int tid) {
#pragma unroll
  for (int r = 0; r < EPT; r++) {
    int s = (SRC == 0) ? locX(tid, r) : (SRC == 1) ? locZ(tid, r) : locY(tid, r);
    sts_el(sh, swz(s), a[r]);
  }
  __syncthreads();
#pragma unroll
  for (int r = 0; r < EPT; r++) {
    int s = (DST == 0) ? locX(tid, r) : (DST == 1) ? locZ(tid, r) : locY(tid, r);
    a[r] = lds_el(sh, swz(s));
  }
}

// --------------------------- P1: hp + init + phi1 + RX1 ----------------------

__global__ void __launch_bounds__(TPB, 2)
pass_init(const float* __restrict__ betas, const float* __restrict__ adj,
          float* __restrict__ out) {
  extern __shared__ float4 sh[];
  __shared__ float2 ph_tab[256];
  __shared__ int s_rm[NQ];
  __shared__ int s_sk[NQ];

  const int tid = threadIdx.x;
  const int b = blockIdx.x >> 5, cb = blockIdx.x & 31;

  { float sv, cv; sincosf((float)tid, &sv, &cv); ph_tab[tid] = make_float2(cv, sv); }
  if (tid < NQ) {
    int m = 0;
    const float* row = adj + (size_t)b * NQ * NQ + tid * NQ;
    for (int v = tid + 1; v < NQ; v++)
      if (row[v] > 0.5f) m |= 1 << (17 - v);
    s_rm[tid] = m;
    s_sk[tid] = __popc(m);
  }
  if (cb == 0 && tid == 0) out[b] = 0.f;
  float cm, sm; sincosf(betas[b * NL + 0], &sm, &cm);
  const u64 cc = pk2(cm, cm), ss = pk2(sm, sm), ns = pk2(-sm, -sm);
  __syncthreads();

  unsigned char* hpb = g_hp + (size_t)b * QDIM;
  uint2* st2 = g_state + (size_t)b * EDIM;

  // ---- hp via bit-slicing (thread covers amps dbase..dbase+31) ----
  const int e0 = dmap<0>(cb, locZ(tid, 0));   // 16 consecutive elements
  const int dbase = e0 * 2;
  unsigned int w[8];
  {
    int ne = 0;
#pragma unroll
    for (int u = 0; u < NQ; u++) ne += s_sk[u];

    int C0 = 0;
    int W2[5] = {0, 0, 0, 0, 0};
#pragma unroll
    for (int u = 0; u < 13; u++) {
      const int m = s_rm[u];
      const int kk = s_sk[u] - 2 * __popc(dbase & m);
      const bool neg = (dbase >> (17 - u)) & 1;
      C0 += neg ? -kk : kk;
      const int d2 = neg ? -2 : 2;
#pragma unroll
      for (int bpos = 0; bpos < 5; bpos++)
        if ((m >> bpos) & 1) W2[bpos] += d2;
    }
    int kk5[5], ml5[5];
#pragma unroll
    for (int k = 0; k < 5; k++) {
      const int u = 13 + k;
      kk5[k] = s_sk[u] - 2 * __popc(dbase & s_rm[u]);
      ml5[k] = s_rm[u] & 31;
    }

    int cr[32];
#pragma unroll
    for (int j = 0; j < 32; j++) {
      int acc = C0;
#pragma unroll
      for (int bpos = 0; bpos < 5; bpos++)
        if (j & (1 << bpos)) acc -= W2[bpos];
#pragma unroll
      for (int k = 0; k < 5; k++) {
        int t2 = kk5[k] - 2 * __popc(j & ml5[k]);
        acc += ((j >> (4 - k)) & 1) ? -t2 : t2;
      }
      cr[j] = acc;
    }
#pragma unroll
    for (int q = 0; q < 8; q++) {
      unsigned int p = 0;
#pragma unroll
      for (int e = 0; e < 4; e++)
        p |= (unsigned int)((ne - cr[q * 4 + e]) >> 1) << (e * 8);
      w[q] = p;
    }
    uint4* hdst = reinterpret_cast<uint4*>(hpb + dbase);
    hdst[0] = make_uint4(w[0], w[1], w[2], w[3]);
    hdst[1] = make_uint4(w[4], w[5], w[6], w[7]);
  }

  // ---- init + phi1 at Z (regs = L0..3, lanes = L4..8) ----
  El a[EPT];
  const float inv = 0.001953125f;  // 1/sqrt(2^18)
#pragma unroll
  for (int r = 0; r < EPT; r++) {
    int k0 = (w[r >> 1] >> ((r & 1) << 4)) & 0xFF;
    int k1 = (w[r >> 1] >> (((r & 1) << 4) + 8)) & 0xFF;
    float2 p0 = ph_tab[k0], p1 = ph_tab[k1];
    a[r].re = pk2(inv * p0.x, inv * p1.x);
    a[r].im = pk2(-inv * p0.y, -inv * p1.y);
  }
  btf4(a, cc, ss, ns);                    // L0..3
  shfl1(a, 1, cc, ss, ns);                // L4 (lane bit 0 at Z)
#pragma unroll
  for (int r = 0; r < EPT; r++) rot2_lane(a[r], cc, ss, ns);  // amp0
  exch<1, 0>(sh, a, tid);                 // Z -> X
  btf4(a, cc, ss, ns);                    // L5..8
  exch<0, 2>(sh, a, tid);                 // X -> Y
  btfE<1>(a, cc, ss, ns);                 // L9
  btfE<2>(a, cc, ss, ns);                 // L10
  btfE<3>(a, cc, ss, ns);                 // L11
#pragma unroll
  for (int r = 0; r < EPT; r++)
    stg_el(st2, dmap<0>(cb, locY(tid, r)), a[r]);   // dense fp16 store
}

// --------------------------- down pass ---------------------------------------

template<int LAY>
__global__ void __launch_bounds__(TPB, 2)
pass_down(const float* __restrict__ betas, int pl) {
  extern __shared__ float4 sh[];
  __shared__ float2 ph_tab[256];

  const int tid = threadIdx.x;
  const int b = blockIdx.x >> 5, cb = blockIdx.x & 31;

  { float sv, cv; sincosf((float)tid, &sv, &cv); ph_tab[tid] = make_float2(cv, sv); }
  float cp, sp, cm, sm;
  sincosf(betas[b * NL + pl], &sp, &cp);
  sincosf(betas[b * NL + pl + 1], &sm, &cm);
  const u64 ccp = pk2(cp, cp), ssp = pk2(sp, sp), nsp = pk2(-sp, -sp);
  const u64 ccm = pk2(cm, cm), ssm = pk2(sm, sm), nsm = pk2(-sm, -sm);

  pdl_wait();

  const unsigned char* hpb = g_hp + (size_t)b * QDIM;
  uint2* st2 = g_state + (size_t)b * EDIM;

  El a[EPT];
  unsigned short hw[EPT];
#pragma unroll
  for (int r = 0; r < EPT; r++) {
    int e = dmap<LAY>(cb, locX(tid, r));   // dense LDG.64
    a[r] = ldg_el(st2, e);
    hw[r] = *reinterpret_cast<const unsigned short*>(hpb + 2 * (size_t)e);
  }
  __syncthreads();                         // ph_tab ready (overlaps loads)

  // pre = L4..8 (amp13..17 @B, amp5..9 @A): regs L5..8 + shfl mask16 (L4)
  btf4(a, ccp, ssp, nsp);
  shfl1(a, 16, ccp, ssp, nsp);
  // phi
#pragma unroll
  for (int r = 0; r < EPT; r++)
    ph2(a[r], ph_tab[hw[r] & 0xFF], ph_tab[hw[r] >> 8]);
  // main: L5..8 at X
  btf4(a, ccm, ssm, nsm);
  // X -> Z
  exch<0, 1>(sh, a, tid);
  // main: L0..3 (Z regs), L4 (lane bit 0 at Z), amp0
  btf4(a, ccm, ssm, nsm);
  shfl1(a, 1, ccm, ssm, nsm);
#pragma unroll
  for (int r = 0; r < EPT; r++) rot2_lane(a[r], ccm, ssm, nsm);
  // Z -> Y
  exch<1, 2>(sh, a, tid);
  // main: L9..11 (Y regs, L8 done at X)
  btfE<1>(a, ccm, ssm, nsm);
  btfE<2>(a, ccm, ssm, nsm);
  btfE<3>(a, ccm, ssm, nsm);
#pragma unroll
  for (int r = 0; r < EPT; r++)
    stg_el(st2, dmap<LAY>(cb, locY(tid, r)), a[r]);   // dense fp16 store
}

// --------------------------- P5: pre RX4 + energy -----------------------------

__global__ void __launch_bounds__(TPB, 2)
pass_energy(const float* __restrict__ betas, float* __restrict__ out) {
  __shared__ float red[TPB / 32];

  const int tid = threadIdx.x;
  const int b = blockIdx.x >> 5, cb = blockIdx.x & 31;

  float cp, sp; sincosf(betas[b * NL + 3], &sp, &cp);
  const u64 ccp = pk2(cp, cp), ssp = pk2(sp, sp), nsp = pk2(-sp, -sp);

  pdl_wait();

  const unsigned char* hpb = g_hp + (size_t)b * QDIM;
  const uint2* st2 = g_state + (size_t)b * EDIM;

  El a[EPT];
  unsigned short hw[EPT];
#pragma unroll
  for (int r = 0; r < EPT; r++) {
    int e = dmap<0>(cb, locX(tid, r));
    a[r] = ldg_el(st2, e);
    hw[r] = *reinterpret_cast<const unsigned short*>(hpb + 2 * (size_t)e);
  }
  // pre RX4 = L4..8
  btf4(a, ccp, ssp, nsp);
  shfl1(a, 16, ccp, ssp, nsp);

  float e = 0.f;
#pragma unroll
  for (int r = 0; r < EPT; r++) {
    u64 p2 = fma2(a[r].im, a[r].im, mul2(a[r].re, a[r].re));
    float p0, p1; upk2(p0, p1, p2);
    e = fmaf(p0, (float)(hw[r] & 0xFF), e);
    e = fmaf(p1, (float)(hw[r] >> 8), e);
  }
#pragma unroll
  for (int o = 16; o; o >>= 1) e += __shfl_down_sync(0xffffffffu, e, o);
  if ((tid & 31) == 0) red[tid >> 5] = e;
  __syncthreads();
  if (tid == 0) {
    float t = 0.f;
#pragma unroll
    for (int i = 0; i < TPB / 32; i++) t += red[i];
    atomicAdd(out + b, t);
  }
}

// --------------------------- launch ----------------------------------------

template<typename K, typename... Args>
static void launch_pdl(K kern, size_t smem, Args... args) {
  cudaLaunchConfig_t cfg = {};
  cfg.gridDim = dim3(BLOCKS, 1, 1);
  cfg.blockDim = dim3(TPB, 1, 1);
  cfg.dynamicSmemBytes = smem;
  cfg.stream = 0;
  cudaLaunchAttribute at[1];
  at[0].id = cudaLaunchAttributeProgrammaticStreamSerialization;
  at[0].val.programmaticStreamSerializationAllowed = 1;
  cfg.attrs = at;
  cfg.numAttrs = 1;
  cudaLaunchKernelEx(&cfg, kern, args...);
}

extern "C" void kernel_launch(void* const* d_in, const int* in_sizes, int n_in,
                              void* d_out, int out_size) {
  const float* betas = (const float*)d_in[0];
  const float* adj   = (const float*)d_in[1];
  if (n_in >= 2 && in_sizes[0] != NB * NL) {
    betas = (const float*)d_in[1];
    adj   = (const float*)d_in[0];
  }
  float* out = (float*)d_out;
  (void)out_size;

  cudaFuncSetAttribute(pass_init,    cudaFuncAttributeMaxDynamicSharedMemorySize, (int)SMEM_BYTES);
  cudaFuncSetAttribute(pass_down<0>, cudaFuncAttributeMaxDynamicSharedMemorySize, (int)SMEM_BYTES);
  cudaFuncSetAttribute(pass_down<1>, cudaFuncAttributeMaxDynamicSharedMemorySize, (int)SMEM_BYTES);

  pass_init<<<BLOCKS, TPB, SMEM_BYTES>>>(betas, adj, out);   // hp + phi1 + RX1
  launch_pdl(pass_down<1>, SMEM_BYTES, betas, 0);  // RX1 13..17, phi2, RX2
  launch_pdl(pass_down<0>, SMEM_BYTES, betas, 1);  // RX2 5..9,   phi3, RX3
  launch_pdl(pass_down<1>, SMEM_BYTES, betas, 2);  // RX3 13..17, phi4, RX4
  launch_pdl(pass_energy, 0, betas, out);          // RX4 5..9 + energy
}

// round 15
// speedup vs baseline: 1.1261x; 1.0296x over previous
#include <cuda_runtime.h>
#include <cuda_fp16.h>
#include <cstdint>
#include <cstddef>

// ---------------------------------------------------------------------------
// QAOA diff quantum simulator, N=18 qubits, B=8, 4 layers.
// R15: R14 (fp16 global state, lane-major dense access, X->Z->Y exchanges,
//      bit-sliced hp, PDL) + PRECOMPUTED FP16 PHASES:
//      P1 stores exp(-i*hp) as fp16x4 per element (8 MB). Down passes read
//      phases via 16 dense LDG.64 (overlapped with state loads) instead of
//      32 random-bank LDS gathers into a per-pass rebuilt 256-entry table;
//      the ph_tab build + its __syncthreads vanish from all down passes.
// Layouts / residencies identical to R13/R14.
// ---------------------------------------------------------------------------

namespace {
constexpr int NQ   = 18;
constexpr int QDIM = 1 << NQ;             // 262144 amps
constexpr int EDIM = QDIM / 2;            // 131072 elements
constexpr int NB   = 8;
constexpr int NL   = 4;
constexpr int TPB  = 256;
constexpr int EPT  = 16;                  // elements per thread
constexpr int CHUNKE = TPB * EPT;         // 4096 elements (12 bits)
constexpr int CPB  = EDIM / CHUNKE;       // 32
constexpr int BLOCKS = NB * CPB;          // 256
constexpr size_t SMEM_BYTES = (size_t)CHUNKE * 16; // 64 KB (fp32 exchange)
}

__device__ __align__(256) uint2 g_state[(size_t)NB * EDIM];      // 8 MB fp16x4
__device__ __align__(256) uint2 g_phase[(size_t)NB * EDIM];      // 8 MB fp16x4
__device__ __align__(16) unsigned char g_hp[(size_t)NB * QDIM];  // 2 MB

// --------------------------- packed f32x2 helpers ---------------------------

using u64 = unsigned long long;

__device__ __forceinline__ u64 pk2(float lo, float hi) {
  u64 d; asm("mov.b64 %0, {%1, %2};" : "=l"(d) : "f"(lo), "f"(hi)); return d;
}
__device__ __forceinline__ void upk2(float& lo, float& hi, u64 v) {
  asm("mov.b64 {%0, %1}, %2;" : "=f"(lo), "=f"(hi) : "l"(v));
}
__device__ __forceinline__ u64 mul2(u64 a, u64 b) {
  u64 d; asm("mul.rn.f32x2 %0, %1, %2;" : "=l"(d) : "l"(a), "l"(b)); return d;
}
__device__ __forceinline__ u64 fma2(u64 a, u64 b, u64 c) {
  u64 d; asm("fma.rn.f32x2 %0, %1, %2, %3;" : "=l"(d) : "l"(a), "l"(b), "l"(c));
  return d;
}
__device__ __forceinline__ u64 swp2(u64 v) {
  float lo, hi; upk2(lo, hi, v); return pk2(hi, lo);
}

struct El { u64 re, im; };

__device__ __forceinline__ void rot2(El& x, El& y, u64 cc, u64 ss, u64 ns) {
  u64 t1 = mul2(ss, y.im);
  u64 t2 = mul2(ns, y.re);
  u64 t3 = mul2(ss, x.im);
  u64 t4 = mul2(ns, x.re);
  x.re = fma2(cc, x.re, t1);
  x.im = fma2(cc, x.im, t2);
  y.re = fma2(cc, y.re, t3);
  y.im = fma2(cc, y.im, t4);
}
__device__ __forceinline__ void rot2_lane(El& x, u64 cc, u64 ss, u64 ns) {
  u64 sre = swp2(x.re), sim = swp2(x.im);
  x.re = fma2(cc, x.re, mul2(ss, sim));
  x.im = fma2(cc, x.im, mul2(ns, sre));
}
__device__ __forceinline__ void rot2_shfl(El& x, int m, u64 cc, u64 ss, u64 ns) {
  u64 pre = __shfl_xor_sync(0xffffffffu, x.re, m);
  u64 pim = __shfl_xor_sync(0xffffffffu, x.im, m);
  x.re = fma2(cc, x.re, mul2(ss, pim));
  x.im = fma2(cc, x.im, mul2(ns, pre));
}

template<int P>
__device__ __forceinline__ void btfE(El* a, u64 cc, u64 ss, u64 ns) {
#pragma unroll
  for (int h = 0; h < EPT / 2; h++) {
    int i0 = ((h >> P) << (P + 1)) | (h & ((1 << P) - 1));
    rot2(a[i0], a[i0 | (1 << P)], cc, ss, ns);
  }
}
__device__ __forceinline__ void btf4(El* a, u64 cc, u64 ss, u64 ns) {
  btfE<0>(a, cc, ss, ns); btfE<1>(a, cc, ss, ns);
  btfE<2>(a, cc, ss, ns); btfE<3>(a, cc, ss, ns);
}
__device__ __forceinline__ void shfl1(El* a, int m, u64 cc, u64 ss, u64 ns) {
#pragma unroll
  for (int r = 0; r < EPT; r++) rot2_shfl(a[r], m, cc, ss, ns);
}

// exp(-i k) with (cos,sin) pairs p0 (amp lo), p1 (amp hi)
__device__ __forceinline__ void ph2(El& x, float2 p0, float2 p1) {
  u64 C  = pk2(p0.x, p1.x);
  u64 S  = pk2(p0.y, p1.y);
  u64 nS = pk2(-p0.y, -p1.y);
  u64 t = mul2(S, x.im);
  u64 u = mul2(nS, x.re);
  x.re = fma2(C, x.re, t);
  x.im = fma2(C, x.im, u);
}

// --------------------------- mappings ---------------------------------------

__device__ __forceinline__ int swz(int s) { return s ^ ((s >> 4) & 15); }

template<int LAY>
__device__ __forceinline__ int dmap(int cb, int L) {
  if (LAY == 0)   // A: cb = e12..16 (amp13..17)
    return (cb << 12) | L;
  else            // B: L0..3->e0..3, cb->e4..8, L9..11->e9..11,
                  //    L4->e12, L5..8->e13..16
    return (L & 15) | (cb << 4) | (((L >> 9) & 7) << 9)
         | (((L >> 4) & 1) << 12) | (((L >> 5) & 15) << 13);
}
__device__ __forceinline__ int locX(int t, int r) { return (t & 31) | (r << 5) | ((t >> 5) << 9); }
__device__ __forceinline__ int locY(int t, int r) { return t | (r << 8); }
__device__ __forceinline__ int locZ(int t, int r) { return r | ((t & 31) << 4) | ((t >> 5) << 9); }

// --------------------------- element I/O -------------------------------------

// global state (fp16x4)
__device__ __forceinline__ El ldg_el(const uint2* p, int e) {
  uint2 v = p[e];
  __half2 hre = *reinterpret_cast<__half2*>(&v.x);
  __half2 him = *reinterpret_cast<__half2*>(&v.y);
  float2 fre = __half22float2(hre);
  float2 fim = __half22float2(him);
  El x; x.re = pk2(fre.x, fre.y); x.im = pk2(fim.x, fim.y); return x;
}
__device__ __forceinline__ void stg_el(uint2* p, int e, El x) {
  float r0, r1, i0, i1;
  upk2(r0, r1, x.re);
  upk2(i0, i1, x.im);
  __half2 hre = __floats2half2_rn(r0, r1);
  __half2 him = __floats2half2_rn(i0, i1);
  uint2 v;
  v.x = *reinterpret_cast<unsigned int*>(&hre);
  v.y = *reinterpret_cast<unsigned int*>(&him);
  p[e] = v;
}
// shared (fp32)
__device__ __forceinline__ El lds_el(const float4* p, int s) {
  float4 v = p[s];
  El x; x.re = pk2(v.x, v.y); x.im = pk2(v.z, v.w); return x;
}
__device__ __forceinline__ void sts_el(float4* p, int s, El x) {
  float4 v; upk2(v.x, v.y, x.re); upk2(v.z, v.w, x.im);
  p[s] = v;
}

__device__ __forceinline__ void pdl_wait() {
  asm volatile("griddepcontrol.wait;" ::: "memory");
}

// exchange helper: SRC/DST: 0 = X, 1 = Z, 2 = Y
template<int SRC, int DST>
__device__ __forceinline__ void exch(float4* sh, El* a, int tid) {
#pragma unroll
  for (int r = 0; r < EPT; r++) {
    int s = (SRC == 0) ? locX(tid, r) : (SRC == 1) ? locZ(tid, r) : locY(tid, r);
    sts_el(sh, swz(s), a[r]);
  }
  __syncthreads();
#pragma unroll
  for (int r = 0; r < EPT; r++) {
    int s = (DST == 0) ? locX(tid, r) : (DST == 1) ? locZ(tid, r) : locY(tid, r);
    a[r] = lds_el(sh, swz(s));
  }
}

// --------------------------- P1: hp + phases + init + phi1 + RX1 -------------

__global__ void __launch_bounds__(TPB, 2)
pass_init(const float* __restrict__ betas, const float* __restrict__ adj,
          float* __restrict__ out) {
  extern __shared__ float4 sh[];
  __shared__ float2 ph_tab[256];
  __shared__ int s_rm[NQ];
  __shared__ int s_sk[NQ];

  const int tid = threadIdx.x;
  const int b = blockIdx.x >> 5, cb = blockIdx.x & 31;

  { float sv, cv; sincosf((float)tid, &sv, &cv); ph_tab[tid] = make_float2(cv, sv); }
  if (tid < NQ) {
    int m = 0;
    const float* row = adj + (size_t)b * NQ * NQ + tid * NQ;
    for (int v = tid + 1; v < NQ; v++)
      if (row[v] > 0.5f) m |= 1 << (17 - v);
    s_rm[tid] = m;
    s_sk[tid] = __popc(m);
  }
  if (cb == 0 && tid == 0) out[b] = 0.f;
  float cm, sm; sincosf(betas[b * NL + 0], &sm, &cm);
  const u64 cc = pk2(cm, cm), ss = pk2(sm, sm), ns = pk2(-sm, -sm);
  __syncthreads();

  unsigned char* hpb = g_hp + (size_t)b * QDIM;
  uint2* st2 = g_state + (size_t)b * EDIM;
  uint2* phb = g_phase + (size_t)b * EDIM;

  // ---- hp via bit-slicing (thread covers amps dbase..dbase+31) ----
  const int e0 = dmap<0>(cb, locZ(tid, 0));   // 16 consecutive elements
  const int dbase = e0 * 2;
  unsigned int w[8];
  {
    int ne = 0;
#pragma unroll
    for (int u = 0; u < NQ; u++) ne += s_sk[u];

    int C0 = 0;
    int W2[5] = {0, 0, 0, 0, 0};
#pragma unroll
    for (int u = 0; u < 13; u++) {
      const int m = s_rm[u];
      const int kk = s_sk[u] - 2 * __popc(dbase & m);
      const bool neg = (dbase >> (17 - u)) & 1;
      C0 += neg ? -kk : kk;
      const int d2 = neg ? -2 : 2;
#pragma unroll
      for (int bpos = 0; bpos < 5; bpos++)
        if ((m >> bpos) & 1) W2[bpos] += d2;
    }
    int kk5[5], ml5[5];
#pragma unroll
    for (int k = 0; k < 5; k++) {
      const int u = 13 + k;
      kk5[k] = s_sk[u] - 2 * __popc(dbase & s_rm[u]);
      ml5[k] = s_rm[u] & 31;
    }

    int cr[32];
#pragma unroll
    for (int j = 0; j < 32; j++) {
      int acc = C0;
#pragma unroll
      for (int bpos = 0; bpos < 5; bpos++)
        if (j & (1 << bpos)) acc -= W2[bpos];
#pragma unroll
      for (int k = 0; k < 5; k++) {
        int t2 = kk5[k] - 2 * __popc(j & ml5[k]);
        acc += ((j >> (4 - k)) & 1) ? -t2 : t2;
      }
      cr[j] = acc;
    }
#pragma unroll
    for (int q = 0; q < 8; q++) {
      unsigned int p = 0;
#pragma unroll
      for (int e = 0; e < 4; e++)
        p |= (unsigned int)((ne - cr[q * 4 + e]) >> 1) << (e * 8);
      w[q] = p;
    }
    uint4* hdst = reinterpret_cast<uint4*>(hpb + dbase);
    hdst[0] = make_uint4(w[0], w[1], w[2], w[3]);
    hdst[1] = make_uint4(w[4], w[5], w[6], w[7]);
  }

  // ---- init + phi1 at Z (regs = L0..3) + phase-table export ----
  El a[EPT];
  const float inv = 0.001953125f;  // 1/sqrt(2^18)
#pragma unroll
  for (int r = 0; r < EPT; r++) {
    int k0 = (w[r >> 1] >> ((r & 1) << 4)) & 0xFF;         // hp(amp 2r)
    int k1 = (w[r >> 1] >> (((r & 1) << 4) + 8)) & 0xFF;   // hp(amp 2r+1)
    float2 p0 = ph_tab[k0], p1 = ph_tab[k1];
    // export exp(-i k) as fp16x4 {cos0,sin0,cos1,sin1} for down passes
    __half2 h0 = __floats2half2_rn(p0.x, p0.y);
    __half2 h1 = __floats2half2_rn(p1.x, p1.y);
    uint2 pv;
    pv.x = *reinterpret_cast<unsigned int*>(&h0);
    pv.y = *reinterpret_cast<unsigned int*>(&h1);
    phb[e0 + r] = pv;                                       // dense
    a[r].re = pk2(inv * p0.x, inv * p1.x);
    a[r].im = pk2(-inv * p0.y, -inv * p1.y);
  }
  btf4(a, cc, ss, ns);                    // L0..3
  shfl1(a, 1, cc, ss, ns);                // L4 (lane bit 0 at Z)
#pragma unroll
  for (int r = 0; r < EPT; r++) rot2_lane(a[r], cc, ss, ns);  // amp0
  exch<1, 0>(sh, a, tid);                 // Z -> X
  btf4(a, cc, ss, ns);                    // L5..8
  exch<0, 2>(sh, a, tid);                 // X -> Y
  btfE<1>(a, cc, ss, ns);                 // L9
  btfE<2>(a, cc, ss, ns);                 // L10
  btfE<3>(a, cc, ss, ns);                 // L11
#pragma unroll
  for (int r = 0; r < EPT; r++)
    stg_el(st2, dmap<0>(cb, locY(tid, r)), a[r]);   // dense fp16 store
}

// --------------------------- down pass ---------------------------------------

template<int LAY>
__global__ void __launch_bounds__(TPB, 2)
pass_down(const float* __restrict__ betas, int pl) {
  extern __shared__ float4 sh[];

  const int tid = threadIdx.x;
  const int b = blockIdx.x >> 5, cb = blockIdx.x & 31;

  float cp, sp, cm, sm;
  sincosf(betas[b * NL + pl], &sp, &cp);
  sincosf(betas[b * NL + pl + 1], &sm, &cm);
  const u64 ccp = pk2(cp, cp), ssp = pk2(sp, sp), nsp = pk2(-sp, -sp);
  const u64 ccm = pk2(cm, cm), ssm = pk2(sm, sm), nsm = pk2(-sm, -sm);

  pdl_wait();

  const uint2* phb = g_phase + (size_t)b * EDIM;
  uint2* st2 = g_state + (size_t)b * EDIM;

  El a[EPT];
  uint2 pw[EPT];
#pragma unroll
  for (int r = 0; r < EPT; r++) {
    int e = dmap<LAY>(cb, locX(tid, r));   // dense LDG.64
    a[r] = ldg_el(st2, e);
    pw[r] = phb[e];                        // dense LDG.64, same index
  }

  // pre = L4..8 (amp13..17 @B, amp5..9 @A): regs L5..8 + shfl mask16 (L4)
  btf4(a, ccp, ssp, nsp);
  shfl1(a, 16, ccp, ssp, nsp);
  // phi: precomputed fp16 phases
#pragma unroll
  for (int r = 0; r < EPT; r++) {
    __half2 h0 = *reinterpret_cast<__half2*>(&pw[r].x);
    __half2 h1 = *reinterpret_cast<__half2*>(&pw[r].y);
    ph2(a[r], __half22float2(h0), __half22float2(h1));
  }
  // main: L5..8 at X
  btf4(a, ccm, ssm, nsm);
  // X -> Z
  exch<0, 1>(sh, a, tid);
  // main: L0..3 (Z regs), L4 (lane bit 0 at Z), amp0
  btf4(a, ccm, ssm, nsm);
  shfl1(a, 1, ccm, ssm, nsm);
#pragma unroll
  for (int r = 0; r < EPT; r++) rot2_lane(a[r], ccm, ssm, nsm);
  // Z -> Y
  exch<1, 2>(sh, a, tid);
  // main: L9..11 (Y regs, L8 done at X)
  btfE<1>(a, ccm, ssm, nsm);
  btfE<2>(a, ccm, ssm, nsm);
  btfE<3>(a, ccm, ssm, nsm);
#pragma unroll
  for (int r = 0; r < EPT; r++)
    stg_el(st2, dmap<LAY>(cb, locY(tid, r)), a[r]);   // dense fp16 store
}

// --------------------------- P5: pre RX4 + energy -----------------------------

__global__ void __launch_bounds__(TPB, 2)
pass_energy(const float* __restrict__ betas, float* __restrict__ out) {
  __shared__ float red[TPB / 32];

  const int tid = threadIdx.x;
  const int b = blockIdx.x >> 5, cb = blockIdx.x & 31;

  float cp, sp; sincosf(betas[b * NL + 3], &sp, &cp);
  const u64 ccp = pk2(cp, cp), ssp = pk2(sp, sp), nsp = pk2(-sp, -sp);

  pdl_wait();

  const unsigned char* hpb = g_hp + (size_t)b * QDIM;
  const uint2* st2 = g_state + (size_t)b * EDIM;

  El a[EPT];
  unsigned short hw[EPT];
#pragma unroll
  for (int r = 0; r < EPT; r++) {
    int e = dmap<0>(cb, locX(tid, r));
    a[r] = ldg_el(st2, e);
    hw[r] = *reinterpret_cast<const unsigned short*>(hpb + 2 * (size_t)e);
  }
  // pre RX4 = L4..8
  btf4(a, ccp, ssp, nsp);
  shfl1(a, 16, ccp, ssp, nsp);

  float e = 0.f;
#pragma unroll
  for (int r = 0; r < EPT; r++) {
    u64 p2 = fma2(a[r].im, a[r].im, mul2(a[r].re, a[r].re));
    float p0, p1; upk2(p0, p1, p2);
    e = fmaf(p0, (float)(hw[r] & 0xFF), e);
    e = fmaf(p1, (float)(hw[r] >> 8), e);
  }
#pragma unroll
  for (int o = 16; o; o >>= 1) e += __shfl_down_sync(0xffffffffu, e, o);
  if ((tid & 31) == 0) red[tid >> 5] = e;
  __syncthreads();
  if (tid == 0) {
    float t = 0.f;
#pragma unroll
    for (int i = 0; i < TPB / 32; i++) t += red[i];
    atomicAdd(out + b, t);
  }
}

// --------------------------- launch ----------------------------------------

template<typename K, typename... Args>
static void launch_pdl(K kern, size_t smem, Args... args) {
  cudaLaunchConfig_t cfg = {};
  cfg.gridDim = dim3(BLOCKS, 1, 1);
  cfg.blockDim = dim3(TPB, 1, 1);
  cfg.dynamicSmemBytes = smem;
  cfg.stream = 0;
  cudaLaunchAttribute at[1];
  at[0].id = cudaLaunchAttributeProgrammaticStreamSerialization;
  at[0].val.programmaticStreamSerializationAllowed = 1;
  cfg.attrs = at;
  cfg.numAttrs = 1;
  cudaLaunchKernelEx(&cfg, kern, args...);
}

extern "C" void kernel_launch(void* const* d_in, const int* in_sizes, int n_in,
                              void* d_out, int out_size) {
  const float* betas = (const float*)d_in[0];
  const float* adj   = (const float*)d_in[1];
  if (n_in >= 2 && in_sizes[0] != NB * NL) {
    betas = (const float*)d_in[1];
    adj   = (const float*)d_in[0];
  }
  float* out = (float*)d_out;
  (void)out_size;

  cudaFuncSetAttribute(pass_init,    cudaFuncAttributeMaxDynamicSharedMemorySize, (int)SMEM_BYTES);
  cudaFuncSetAttribute(pass_down<0>, cudaFuncAttributeMaxDynamicSharedMemorySize, (int)SMEM_BYTES);
  cudaFuncSetAttribute(pass_down<1>, cudaFuncAttributeMaxDynamicSharedMemorySize, (int)SMEM_BYTES);

  pass_init<<<BLOCKS, TPB, SMEM_BYTES>>>(betas, adj, out);   // hp + phases + phi1 + RX1
  launch_pdl(pass_down<1>, SMEM_BYTES, betas, 0);  // RX1 13..17, phi2, RX2
  launch_pdl(pass_down<0>, SMEM_BYTES, betas, 1);  // RX2 5..9,   phi3, RX3
  launch_pdl(pass_down<1>, SMEM_BYTES, betas, 2);  // RX3 13..17, phi4, RX4
  launch_pdl(pass_energy, 0, betas, out);          // RX4 5..9 + energy
}

// round 16
// speedup vs baseline: 1.1848x; 1.0521x over previous
#include <cuda_runtime.h>
#include <cuda_fp16.h>
#include <cstdint>
#include <cstddef>

// ---------------------------------------------------------------------------
// QAOA diff quantum simulator, N=18 qubits, B=8, 4 layers.
// R16: R15 (fp16 global state + precomputed fp16 phases, lane-major dense
//      access, X->Z->Y exchanges, bit-sliced hp, PDL) +
//   (a) X<->Z exchanges are WARP-LOCAL (warp bits L9..11 fixed, swizzle only
//       mixes L0..7) -> __syncwarp instead of __syncthreads (1 CTA barrier
//       per down pass instead of 2);
//   (b) explicit griddepcontrol.launch_dependents right after each pass's
//       final STG -> dependent grid schedules during the primary's drain.
// Layouts / residencies identical to R13/R14/R15.
// ---------------------------------------------------------------------------

namespace {
constexpr int NQ   = 18;
constexpr int QDIM = 1 << NQ;             // 262144 amps
constexpr int EDIM = QDIM / 2;            // 131072 elements
constexpr int NB   = 8;
constexpr int NL   = 4;
constexpr int TPB  = 256;
constexpr int EPT  = 16;                  // elements per thread
constexpr int CHUNKE = TPB * EPT;         // 4096 elements (12 bits)
constexpr int CPB  = EDIM / CHUNKE;       // 32
constexpr int BLOCKS = NB * CPB;          // 256
constexpr size_t SMEM_BYTES = (size_t)CHUNKE * 16; // 64 KB (fp32 exchange)
}

__device__ __align__(256) uint2 g_state[(size_t)NB * EDIM];      // 8 MB fp16x4
__device__ __align__(256) uint2 g_phase[(size_t)NB * EDIM];      // 8 MB fp16x4
__device__ __align__(16) unsigned char g_hp[(size_t)NB * QDIM];  // 2 MB

// --------------------------- packed f32x2 helpers ---------------------------

using u64 = unsigned long long;

__device__ __forceinline__ u64 pk2(float lo, float hi) {
  u64 d; asm("mov.b64 %0, {%1, %2};" : "=l"(d) : "f"(lo), "f"(hi)); return d;
}
__device__ __forceinline__ void upk2(float& lo, float& hi, u64 v) {
  asm("mov.b64 {%0, %1}, %2;" : "=f"(lo), "=f"(hi) : "l"(v));
}
__device__ __forceinline__ u64 mul2(u64 a, u64 b) {
  u64 d; asm("mul.rn.f32x2 %0, %1, %2;" : "=l"(d) : "l"(a), "l"(b)); return d;
}
__device__ __forceinline__ u64 fma2(u64 a, u64 b, u64 c) {
  u64 d; asm("fma.rn.f32x2 %0, %1, %2, %3;" : "=l"(d) : "l"(a), "l"(b), "l"(c));
  return d;
}
__device__ __forceinline__ u64 swp2(u64 v) {
  float lo, hi; upk2(lo, hi, v); return pk2(hi, lo);
}

struct El { u64 re, im; };

__device__ __forceinline__ void rot2(El& x, El& y, u64 cc, u64 ss, u64 ns) {
  u64 t1 = mul2(ss, y.im);
  u64 t2 = mul2(ns, y.re);
  u64 t3 = mul2(ss, x.im);
  u64 t4 = mul2(ns, x.re);
  x.re = fma2(cc, x.re, t1);
  x.im = fma2(cc, x.im, t2);
  y.re = fma2(cc, y.re, t3);
  y.im = fma2(cc, y.im, t4);
}
__device__ __forceinline__ void rot2_lane(El& x, u64 cc, u64 ss, u64 ns) {
  u64 sre = swp2(x.re), sim = swp2(x.im);
  x.re = fma2(cc, x.re, mul2(ss, sim));
  x.im = fma2(cc, x.im, mul2(ns, sre));
}
__device__ __forceinline__ void rot2_shfl(El& x, int m, u64 cc, u64 ss, u64 ns) {
  u64 pre = __shfl_xor_sync(0xffffffffu, x.re, m);
  u64 pim = __shfl_xor_sync(0xffffffffu, x.im, m);
  x.re = fma2(cc, x.re, mul2(ss, pim));
  x.im = fma2(cc, x.im, mul2(ns, pre));
}

template<int P>
__device__ __forceinline__ void btfE(El* a, u64 cc, u64 ss, u64 ns) {
#pragma unroll
  for (int h = 0; h < EPT / 2; h++) {
    int i0 = ((h >> P) << (P + 1)) | (h & ((1 << P) - 1));
    rot2(a[i0], a[i0 | (1 << P)], cc, ss, ns);
  }
}
__device__ __forceinline__ void btf4(El* a, u64 cc, u64 ss, u64 ns) {
  btfE<0>(a, cc, ss, ns); btfE<1>(a, cc, ss, ns);
  btfE<2>(a, cc, ss, ns); btfE<3>(a, cc, ss, ns);
}
__device__ __forceinline__ void shfl1(El* a, int m, u64 cc, u64 ss, u64 ns) {
#pragma unroll
  for (int r = 0; r < EPT; r++) rot2_shfl(a[r], m, cc, ss, ns);
}

// exp(-i k) with (cos,sin) pairs p0 (amp lo), p1 (amp hi)
__device__ __forceinline__ void ph2(El& x, float2 p0, float2 p1) {
  u64 C  = pk2(p0.x, p1.x);
  u64 S  = pk2(p0.y, p1.y);
  u64 nS = pk2(-p0.y, -p1.y);
  u64 t = mul2(S, x.im);
  u64 u = mul2(nS, x.re);
  x.re = fma2(C, x.re, t);
  x.im = fma2(C, x.im, u);
}

// --------------------------- mappings ---------------------------------------

__device__ __forceinline__ int swz(int s) { return s ^ ((s >> 4) & 15); }

template<int LAY>
__device__ __forceinline__ int dmap(int cb, int L) {
  if (LAY == 0)   // A: cb = e12..16 (amp13..17)
    return (cb << 12) | L;
  else            // B: L0..3->e0..3, cb->e4..8, L9..11->e9..11,
                  //    L4->e12, L5..8->e13..16
    return (L & 15) | (cb << 4) | (((L >> 9) & 7) << 9)
         | (((L >> 4) & 1) << 12) | (((L >> 5) & 15) << 13);
}
__device__ __forceinline__ int locX(int t, int r) { return (t & 31) | (r << 5) | ((t >> 5) << 9); }
__device__ __forceinline__ int locY(int t, int r) { return t | (r << 8); }
__device__ __forceinline__ int locZ(int t, int r) { return r | ((t & 31) << 4) | ((t >> 5) << 9); }

// --------------------------- element I/O -------------------------------------

// global state (fp16x4)
__device__ __forceinline__ El ldg_el(const uint2* p, int e) {
  uint2 v = p[e];
  __half2 hre = *reinterpret_cast<__half2*>(&v.x);
  __half2 him = *reinterpret_cast<__half2*>(&v.y);
  float2 fre = __half22float2(hre);
  float2 fim = __half22float2(him);
  El x; x.re = pk2(fre.x, fre.y); x.im = pk2(fim.x, fim.y); return x;
}
__device__ __forceinline__ void stg_el(uint2* p, int e, El x) {
  float r0, r1, i0, i1;
  upk2(r0, r1, x.re);
  upk2(i0, i1, x.im);
  __half2 hre = __floats2half2_rn(r0, r1);
  __half2 him = __floats2half2_rn(i0, i1);
  uint2 v;
  v.x = *reinterpret_cast<unsigned int*>(&hre);
  v.y = *reinterpret_cast<unsigned int*>(&him);
  p[e] = v;
}
// shared (fp32)
__device__ __forceinline__ El lds_el(const float4* p, int s) {
  float4 v = p[s];
  El x; x.re = pk2(v.x, v.y); x.im = pk2(v.z, v.w); return x;
}
__device__ __forceinline__ void sts_el(float4* p, int s, El x) {
  float4 v; upk2(v.x, v.y, x.re); upk2(v.z, v.w, x.im);
  p[s] = v;
}

__device__ __forceinline__ void pdl_wait() {
  asm volatile("griddepcontrol.wait;" ::: "memory");
}
__device__ __forceinline__ void pdl_trigger() {
  asm volatile("griddepcontrol.launch_dependents;" ::: "memory");
}

// exchange helper. SRC/DST: 0 = X, 1 = Z, 2 = Y.
// X<->Z keep warp bits (L9..11) fixed and the swizzle only mixes L0..7,
// so those exchanges are warp-local -> __syncwarp suffices.
template<int SRC, int DST>
__device__ __forceinline__ void exch(float4* sh, El* a, int tid) {
  constexpr bool warp_local = (SRC != 2) && (DST != 2);
#pragma unroll
  for (int r = 0; r < EPT; r++) {
    int s = (SRC == 0) ? locX(tid, r) : (SRC == 1) ? locZ(tid, r) : locY(tid, r);
    sts_el(sh, swz(s), a[r]);
  }
  if (warp_local) __syncwarp();
  else            __syncthreads();
#pragma unroll
  for (int r = 0; r < EPT; r++) {
    int s = (DST == 0) ? locX(tid, r) : (DST == 1) ? locZ(tid, r) : locY(tid, r);
    a[r] = lds_el(sh, swz(s));
  }
}

// --------------------------- P1: hp + phases + init + phi1 + RX1 -------------

__global__ void __launch_bounds__(TPB, 2)
pass_init(const float* __restrict__ betas, const float* __restrict__ adj,
          float* __restrict__ out) {
  extern __shared__ float4 sh[];
  __shared__ float2 ph_tab[256];
  __shared__ int s_rm[NQ];
  __shared__ int s_sk[NQ];

  const int tid = threadIdx.x;
  const int b = blockIdx.x >> 5, cb = blockIdx.x & 31;

  { float sv, cv; sincosf((float)tid, &sv, &cv); ph_tab[tid] = make_float2(cv, sv); }
  if (tid < NQ) {
    int m = 0;
    const float* row = adj + (size_t)b * NQ * NQ + tid * NQ;
    for (int v = tid + 1; v < NQ; v++)
      if (row[v] > 0.5f) m |= 1 << (17 - v);
    s_rm[tid] = m;
    s_sk[tid] = __popc(m);
  }
  if (cb == 0 && tid == 0) out[b] = 0.f;
  float cm, sm; sincosf(betas[b * NL + 0], &sm, &cm);
  const u64 cc = pk2(cm, cm), ss = pk2(sm, sm), ns = pk2(-sm, -sm);
  __syncthreads();

  unsigned char* hpb = g_hp + (size_t)b * QDIM;
  uint2* st2 = g_state + (size_t)b * EDIM;
  uint2* phb = g_phase + (size_t)b * EDIM;

  // ---- hp via bit-slicing (thread covers amps dbase..dbase+31) ----
  const int e0 = dmap<0>(cb, locZ(tid, 0));   // 16 consecutive elements
  const int dbase = e0 * 2;
  unsigned int w[8];
  {
    int ne = 0;
#pragma unroll
    for (int u = 0; u < NQ; u++) ne += s_sk[u];

    int C0 = 0;
    int W2[5] = {0, 0, 0, 0, 0};
#pragma unroll
    for (int u = 0; u < 13; u++) {
      const int m = s_rm[u];
      const int kk = s_sk[u] - 2 * __popc(dbase & m);
      const bool neg = (dbase >> (17 - u)) & 1;
      C0 += neg ? -kk : kk;
      const int d2 = neg ? -2 : 2;
#pragma unroll
      for (int bpos = 0; bpos < 5; bpos++)
        if ((m >> bpos) & 1) W2[bpos] += d2;
    }
    int kk5[5], ml5[5];
#pragma unroll
    for (int k = 0; k < 5; k++) {
      const int u = 13 + k;
      kk5[k] = s_sk[u] - 2 * __popc(dbase & s_rm[u]);
      ml5[k] = s_rm[u] & 31;
    }

    int cr[32];
#pragma unroll
    for (int j = 0; j < 32; j++) {
      int acc = C0;
#pragma unroll
      for (int bpos = 0; bpos < 5; bpos++)
        if (j & (1 << bpos)) acc -= W2[bpos];
#pragma unroll
      for (int k = 0; k < 5; k++) {
        int t2 = kk5[k] - 2 * __popc(j & ml5[k]);
        acc += ((j >> (4 - k)) & 1) ? -t2 : t2;
      }
      cr[j] = acc;
    }
#pragma unroll
    for (int q = 0; q < 8; q++) {
      unsigned int p = 0;
#pragma unroll
      for (int e = 0; e < 4; e++)
        p |= (unsigned int)((ne - cr[q * 4 + e]) >> 1) << (e * 8);
      w[q] = p;
    }
    uint4* hdst = reinterpret_cast<uint4*>(hpb + dbase);
    hdst[0] = make_uint4(w[0], w[1], w[2], w[3]);
    hdst[1] = make_uint4(w[4], w[5], w[6], w[7]);
  }

  // ---- init + phi1 at Z (regs = L0..3) + phase-table export ----
  El a[EPT];
  const float inv = 0.001953125f;  // 1/sqrt(2^18)
#pragma unroll
  for (int r = 0; r < EPT; r++) {
    int k0 = (w[r >> 1] >> ((r & 1) << 4)) & 0xFF;         // hp(amp 2r)
    int k1 = (w[r >> 1] >> (((r & 1) << 4) + 8)) & 0xFF;   // hp(amp 2r+1)
    float2 p0 = ph_tab[k0], p1 = ph_tab[k1];
    // export exp(-i k) as fp16x4 {cos0,sin0,cos1,sin1} for down passes
    __half2 h0 = __floats2half2_rn(p0.x, p0.y);
    __half2 h1 = __floats2half2_rn(p1.x, p1.y);
    uint2 pv;
    pv.x = *reinterpret_cast<unsigned int*>(&h0);
    pv.y = *reinterpret_cast<unsigned int*>(&h1);
    phb[e0 + r] = pv;                                       // dense
    a[r].re = pk2(inv * p0.x, inv * p1.x);
    a[r].im = pk2(-inv * p0.y, -inv * p1.y);
  }
  btf4(a, cc, ss, ns);                    // L0..3
  shfl1(a, 1, cc, ss, ns);                // L4 (lane bit 0 at Z)
#pragma unroll
  for (int r = 0; r < EPT; r++) rot2_lane(a[r], cc, ss, ns);  // amp0
  exch<1, 0>(sh, a, tid);                 // Z -> X (warp-local)
  btf4(a, cc, ss, ns);                    // L5..8
  exch<0, 2>(sh, a, tid);                 // X -> Y (cross-warp)
  btfE<1>(a, cc, ss, ns);                 // L9
  btfE<2>(a, cc, ss, ns);                 // L10
  btfE<3>(a, cc, ss, ns);                 // L11
#pragma unroll
  for (int r = 0; r < EPT; r++)
    stg_el(st2, dmap<0>(cb, locY(tid, r)), a[r]);   // dense fp16 store
  pdl_trigger();
}

// --------------------------- down pass ---------------------------------------

template<int LAY>
__global__ void __launch_bounds__(TPB, 2)
pass_down(const float* __restrict__ betas, int pl) {
  extern __shared__ float4 sh[];

  const int tid = threadIdx.x;
  const int b = blockIdx.x >> 5, cb = blockIdx.x & 31;

  float cp, sp, cm, sm;
  sincosf(betas[b * NL + pl], &sp, &cp);
  sincosf(betas[b * NL + pl + 1], &sm, &cm);
  const u64 ccp = pk2(cp, cp), ssp = pk2(sp, sp), nsp = pk2(-sp, -sp);
  const u64 ccm = pk2(cm, cm), ssm = pk2(sm, sm), nsm = pk2(-sm, -sm);

  pdl_wait();

  const uint2* phb = g_phase + (size_t)b * EDIM;
  uint2* st2 = g_state + (size_t)b * EDIM;

  El a[EPT];
  uint2 pw[EPT];
#pragma unroll
  for (int r = 0; r < EPT; r++) {
    int e = dmap<LAY>(cb, locX(tid, r));   // dense LDG.64
    a[r] = ldg_el(st2, e);
    pw[r] = phb[e];                        // dense LDG.64, same index
  }

  // pre = L4..8 (amp13..17 @B, amp5..9 @A): regs L5..8 + shfl mask16 (L4)
  btf4(a, ccp, ssp, nsp);
  shfl1(a, 16, ccp, ssp, nsp);
  // phi: precomputed fp16 phases
#pragma unroll
  for (int r = 0; r < EPT; r++) {
    __half2 h0 = *reinterpret_cast<__half2*>(&pw[r].x);
    __half2 h1 = *reinterpret_cast<__half2*>(&pw[r].y);
    ph2(a[r], __half22float2(h0), __half22float2(h1));
  }
  // main: L5..8 at X
  btf4(a, ccm, ssm, nsm);
  // X -> Z (warp-local: __syncwarp only)
  exch<0, 1>(sh, a, tid);
  // main: L0..3 (Z regs), L4 (lane bit 0 at Z), amp0
  btf4(a, ccm, ssm, nsm);
  shfl1(a, 1, ccm, ssm, nsm);
#pragma unroll
  for (int r = 0; r < EPT; r++) rot2_lane(a[r], ccm, ssm, nsm);
  // Z -> Y (cross-warp)
  exch<1, 2>(sh, a, tid);
  // main: L9..11 (Y regs, L8 done at X)
  btfE<1>(a, ccm, ssm, nsm);
  btfE<2>(a, ccm, ssm, nsm);
  btfE<3>(a, ccm, ssm, nsm);
#pragma unroll
  for (int r = 0; r < EPT; r++)
    stg_el(st2, dmap<LAY>(cb, locY(tid, r)), a[r]);   // dense fp16 store
  pdl_trigger();
}

// --------------------------- P5: pre RX4 + energy -----------------------------

__global__ void __launch_bounds__(TPB, 2)
pass_energy(const float* __restrict__ betas, float* __restrict__ out) {
  __shared__ float red[TPB / 32];

  const int tid = threadIdx.x;
  const int b = blockIdx.x >> 5, cb = blockIdx.x & 31;

  float cp, sp; sincosf(betas[b * NL + 3], &sp, &cp);
  const u64 ccp = pk2(cp, cp), ssp = pk2(sp, sp), nsp = pk2(-sp, -sp);

  pdl_wait();

  const unsigned char* hpb = g_hp + (size_t)b * QDIM;
  const uint2* st2 = g_state + (size_t)b * EDIM;

  El a[EPT];
  unsigned short hw[EPT];
#pragma unroll
  for (int r = 0; r < EPT; r++) {
    int e = dmap<0>(cb, locX(tid, r));
    a[r] = ldg_el(st2, e);
    hw[r] = *reinterpret_cast<const unsigned short*>(hpb + 2 * (size_t)e);
  }
  // pre RX4 = L4..8
  btf4(a, ccp, ssp, nsp);
  shfl1(a, 16, ccp, ssp, nsp);

  float e = 0.f;
#pragma unroll
  for (int r = 0; r < EPT; r++) {
    u64 p2 = fma2(a[r].im, a[r].im, mul2(a[r].re, a[r].re));
    float p0, p1; upk2(p0, p1, p2);
    e = fmaf(p0, (float)(hw[r] & 0xFF), e);
    e = fmaf(p1, (float)(hw[r] >> 8), e);
  }
#pragma unroll
  for (int o = 16; o; o >>= 1) e += __shfl_down_sync(0xffffffffu, e, o);
  if ((tid & 31) == 0) red[tid >> 5] = e;
  __syncthreads();
  if (tid == 0) {
    float t = 0.f;
#pragma unroll
    for (int i = 0; i < TPB / 32; i++) t += red[i];
    atomicAdd(out + b, t);
  }
}

// --------------------------- launch ----------------------------------------

template<typename K, typename... Args>
static void launch_pdl(K kern, size_t smem, Args... args) {
  cudaLaunchConfig_t cfg = {};
  cfg.gridDim = dim3(BLOCKS, 1, 1);
  cfg.blockDim = dim3(TPB, 1, 1);
  cfg.dynamicSmemBytes = smem;
  cfg.stream = 0;
  cudaLaunchAttribute at[1];
  at[0].id = cudaLaunchAttributeProgrammaticStreamSerialization;
  at[0].val.programmaticStreamSerializationAllowed = 1;
  cfg.attrs = at;
  cfg.numAttrs = 1;
  cudaLaunchKernelEx(&cfg, kern, args...);
}

extern "C" void kernel_launch(void* const* d_in, const int* in_sizes, int n_in,
                              void* d_out, int out_size) {
  const float* betas = (const float*)d_in[0];
  const float* adj   = (const float*)d_in[1];
  if (n_in >= 2 && in_sizes[0] != NB * NL) {
    betas = (const float*)d_in[1];
    adj   = (const float*)d_in[0];
  }
  float* out = (float*)d_out;
  (void)out_size;

  cudaFuncSetAttribute(pass_init,    cudaFuncAttributeMaxDynamicSharedMemorySize, (int)SMEM_BYTES);
  cudaFuncSetAttribute(pass_down<0>, cudaFuncAttributeMaxDynamicSharedMemorySize, (int)SMEM_BYTES);
  cudaFuncSetAttribute(pass_down<1>, cudaFuncAttributeMaxDynamicSharedMemorySize, (int)SMEM_BYTES);

  pass_init<<<BLOCKS, TPB, SMEM_BYTES>>>(betas, adj, out);   // hp + phases + phi1 + RX1
  launch_pdl(pass_down<1>, SMEM_BYTES, betas, 0);  // RX1 13..17, phi2, RX2
  launch_pdl(pass_down<0>, SMEM_BYTES, betas, 1);  // RX2 5..9,   phi3, RX3
  launch_pdl(pass_down<1>, SMEM_BYTES, betas, 2);  // RX3 13..17, phi4, RX4
  launch_pdl(pass_energy, 0, betas, out);          // RX4 5..9 + energy
}